// round 13
// baseline (speedup 1.0000x reference)
#include <cuda_runtime.h>
#include <cuda_bf16.h>
#include <cstdint>

#define NN 30000
#define EE 250000
#define IN_F 512
#define HID_F 256
#define OUT_F 128

typedef unsigned long long u64;
typedef __nv_bfloat16 bf16;

// ---------------- scratch (static device globals; no allocs) ----------------
__device__ float g_y[(size_t)12 * NN * HID_F];
__device__ float g_y2[(size_t)12 * NN * OUT_F];
__device__ float g_zd[(size_t)NN * 3 * OUT_F];
__device__ float g_zp[(size_t)NN * 3 * OUT_F];
__device__ float g_rout[12 * NN];
__device__ float g_rin[12 * NN];
__device__ float g_wsum[8];
__device__ int   g_cnts[12 * NN];
__device__ int   g_cnt[12 * NN];
__device__ int   g_base[12 * NN];
__device__ int   g_cur[12 * NN];
__device__ int   g_csrs[(size_t)12 * EE];
__device__ float g_csrw[(size_t)12 * EE];
__device__ __align__(16) bf16 g_x1[(size_t)2 * NN * IN_F];
__device__ __align__(16) bf16 g_x2[(size_t)2 * NN * IN_F];
__device__ __align__(16) bf16 g_h1[(size_t)6 * NN * HID_F];
__device__ __align__(16) bf16 g_h2[(size_t)6 * NN * HID_F];
__device__ __align__(16) bf16 g_za1[(size_t)2 * NN * 3 * OUT_F];
__device__ __align__(16) bf16 g_wt1a[(size_t)12 * HID_F * IN_F];
__device__ __align__(16) bf16 g_wt1b[(size_t)12 * HID_F * IN_F];
__device__ __align__(16) bf16 g_wt2a[(size_t)12 * OUT_F * HID_F];
__device__ __align__(16) bf16 g_wt2b[(size_t)12 * OUT_F * HID_F];
__device__ __align__(16) bf16 g_wpa[(size_t)OUT_F * OUT_F];
__device__ __align__(16) bf16 g_wpb[(size_t)OUT_F * OUT_F];

__device__ __forceinline__ void fma4(float4& a, float w, const float4 v) {
    a.x += w * v.x; a.y += w * v.y; a.z += w * v.z; a.w += w * v.w;
}
__device__ __forceinline__ int u2cr(int u) {
    int ci = u >> 2;
    int c = (ci == 0) ? 0 : (ci == 1 ? 2 : 3);
    return c * 4 + (u & 3);
}

// ---------------- stream handles (created at static init, pre-checkpoint) ----
struct Streams {
    cudaStream_t side = nullptr;
    cudaStream_t sc[3] = {nullptr, nullptr, nullptr};
    cudaEvent_t fork = nullptr, join = nullptr, w1e = nullptr, xe = nullptr;
    cudaEvent_t e1[3] = {nullptr, nullptr, nullptr};
    cudaEvent_t ec[3] = {nullptr, nullptr, nullptr};
    Streams() {
        cudaStreamCreateWithFlags(&side, cudaStreamNonBlocking);
        cudaEventCreateWithFlags(&fork, cudaEventDisableTiming);
        cudaEventCreateWithFlags(&join, cudaEventDisableTiming);
        cudaEventCreateWithFlags(&w1e, cudaEventDisableTiming);
        cudaEventCreateWithFlags(&xe, cudaEventDisableTiming);
        for (int c = 0; c < 3; ++c) {
            cudaStreamCreateWithFlags(&sc[c], cudaStreamNonBlocking);
            cudaEventCreateWithFlags(&e1[c], cudaEventDisableTiming);
            cudaEventCreateWithFlags(&ec[c], cudaEventDisableTiming);
        }
    }
};
static Streams g_ss;

// ---------------- utility kernels ----------------
__global__ void k_zero(float* __restrict__ p, int n) {
    int i = blockIdx.x * blockDim.x + threadIdx.x;
    if (i < n) p[i] = 0.f;
}
__global__ void k_zeroi2(int* __restrict__ a, int* __restrict__ b, int n) {
    int i = blockIdx.x * blockDim.x + threadIdx.x;
    if (i < n) { a[i] = 0; b[i] = 0; }
}

__global__ void k_hist2(const int* __restrict__ src, const int* __restrict__ dst,
                        int* __restrict__ cnts, int* __restrict__ cntd) {
    int i = blockIdx.x * blockDim.x + threadIdx.x;
    if (i >= 12 * EE) return;
    int u = i / EE, e = i - u * EE;
    int cr = u2cr(u);
    atomicAdd(&cnts[u * NN + src[(size_t)cr * EE + e]], 1);
    atomicAdd(&cntd[u * NN + dst[(size_t)cr * EE + e]], 1);
}

__global__ void k_prep(const int* __restrict__ cnts, const int* __restrict__ cntd,
                       float* __restrict__ rout, float* __restrict__ rin) {
    int i = blockIdx.x * blockDim.x + threadIdx.x;
    if (i >= 12 * NN) return;
    rout[i] = rsqrtf((float)max(cnts[i], 1));
    rin[i]  = rsqrtf((float)max(cntd[i], 1));
}

// deterministic exclusive scan per u (12 blocks, 1024 threads)
__global__ void k_scan(const int* __restrict__ cnt, int* __restrict__ base,
                       int* __restrict__ cur) {
    __shared__ int ws[32];
    __shared__ int carry;
    int u = blockIdx.x;
    const int* c = cnt + u * NN;
    int* b = base + u * NN;
    int* q = cur + u * NN;
    int lane = threadIdx.x & 31, w = threadIdx.x >> 5;
    if (threadIdx.x == 0) carry = 0;
    __syncthreads();
    for (int off = 0; off < NN; off += 1024) {
        int i = off + threadIdx.x;
        int v = (i < NN) ? c[i] : 0;
        int s = v;
#pragma unroll
        for (int o = 1; o < 32; o <<= 1) {
            int t = __shfl_up_sync(0xffffffffu, s, o);
            if (lane >= o) s += t;
        }
        if (lane == 31) ws[w] = s;
        __syncthreads();
        if (w == 0) {
            int t2 = ws[lane];
#pragma unroll
            for (int o = 1; o < 32; o <<= 1) {
                int t = __shfl_up_sync(0xffffffffu, t2, o);
                if (lane >= o) t2 += t;
            }
            ws[lane] = t2;
        }
        __syncthreads();
        int excl = s - v + (w > 0 ? ws[w - 1] : 0) + carry;
        if (i < NN) { b[i] = excl; q[i] = excl; }
        __syncthreads();
        if (threadIdx.x == 1023) carry = excl + v;
        __syncthreads();
    }
}

__global__ void k_fill(const int* __restrict__ src, const int* __restrict__ dst,
                       const float* __restrict__ rout, int* __restrict__ cur,
                       int* __restrict__ csrs, float* __restrict__ csrw) {
    int i = blockIdx.x * blockDim.x + threadIdx.x;
    if (i >= 12 * EE) return;
    int u = i / EE, e = i - u * EE;
    int cr = u2cr(u);
    int s = src[(size_t)cr * EE + e];
    int d = dst[(size_t)cr * EE + e];
    int pos = atomicAdd(&cur[u * NN + d], 1);
    csrs[(size_t)u * EE + pos] = s;
    csrw[(size_t)u * EE + pos] = rout[u * NN + s];
}

// split fp32 -> bf16 hi/lo
__global__ void k_split(const float* __restrict__ x, bf16* __restrict__ hi,
                        bf16* __restrict__ lo, int n4) {
    int i = blockIdx.x * blockDim.x + threadIdx.x;
    if (i >= n4) return;
    float4 v = ((const float4*)x)[i];
    bf16 h0 = __float2bfloat16(v.x), h1 = __float2bfloat16(v.y);
    bf16 h2 = __float2bfloat16(v.z), h3 = __float2bfloat16(v.w);
    ((__nv_bfloat162*)hi)[2 * i]     = __halves2bfloat162(h0, h1);
    ((__nv_bfloat162*)hi)[2 * i + 1] = __halves2bfloat162(h2, h3);
    bf16 l0 = __float2bfloat16(v.x - __bfloat162float(h0));
    bf16 l1 = __float2bfloat16(v.y - __bfloat162float(h1));
    bf16 l2 = __float2bfloat16(v.z - __bfloat162float(h2));
    bf16 l3 = __float2bfloat16(v.w - __bfloat162float(h3));
    ((__nv_bfloat162*)lo)[2 * i]     = __halves2bfloat162(l0, l1);
    ((__nv_bfloat162*)lo)[2 * i + 1] = __halves2bfloat162(l2, l3);
}

// transpose+split weights
__global__ void k_wts(const float* __restrict__ W, bf16* __restrict__ t1,
                      bf16* __restrict__ t2, int K, int N) {
    __shared__ float tile[32][33];
    int z = blockIdx.z;
    int cz = z >> 2;
    int c = (cz == 0) ? 0 : (cz == 1 ? 2 : 3);
    const float* Wm = W + (size_t)(c * 4 + (z & 3)) * K * N;
    bf16* o1 = t1 + (size_t)z * K * N;
    bf16* o2 = t2 + (size_t)z * K * N;
    int k0 = blockIdx.y * 32, n0 = blockIdx.x * 32;
    for (int r = threadIdx.y; r < 32; r += 8)
        tile[r][threadIdx.x] = Wm[(size_t)(k0 + r) * N + n0 + threadIdx.x];
    __syncthreads();
    for (int r = threadIdx.y; r < 32; r += 8) {
        float v = tile[threadIdx.x][r];
        bf16 h = __float2bfloat16(v);
        size_t o = (size_t)(n0 + r) * K + k0 + threadIdx.x;
        o1[o] = h;
        o2[o] = __float2bfloat16(v - __bfloat162float(h));
    }
}

__global__ void k_wts1(const float* __restrict__ W, bf16* __restrict__ t1,
                       bf16* __restrict__ t2, int K, int N) {
    __shared__ float tile[32][33];
    int k0 = blockIdx.y * 32, n0 = blockIdx.x * 32;
    for (int r = threadIdx.y; r < 32; r += 8)
        tile[r][threadIdx.x] = W[(size_t)(k0 + r) * N + n0 + threadIdx.x];
    __syncthreads();
    for (int r = threadIdx.y; r < 32; r += 8) {
        float v = tile[threadIdx.x][r];
        bf16 h = __float2bfloat16(v);
        size_t o = (size_t)(n0 + r) * K + k0 + threadIdx.x;
        t1[o] = h;
        t2[o] = __float2bfloat16(v - __bfloat162float(h));
    }
}

// ---------------- mma.sync bf16 GEMM, 128x128 tile (R6 winner) ----------------
__device__ __forceinline__ void mma16816(float* c, const uint32_t* a, const uint32_t* b) {
    asm volatile("mma.sync.aligned.m16n8k16.row.col.f32.bf16.bf16.f32 "
                 "{%0,%1,%2,%3}, {%4,%5,%6,%7}, {%8,%9}, {%0,%1,%2,%3};"
                 : "+f"(c[0]), "+f"(c[1]), "+f"(c[2]), "+f"(c[3])
                 : "r"(a[0]), "r"(a[1]), "r"(a[2]), "r"(a[3]), "r"(b[0]), "r"(b[1]));
}

template <int KK, int NOUT, int CH, int CHAINS, int ATT>
__global__ void __launch_bounds__(256, 2) k_mma(
    const bf16* __restrict__ A1b, const bf16* __restrict__ A2b,
    const bf16* __restrict__ Bt1, const bf16* __restrict__ Bt2,
    float* __restrict__ Y, int M, int u0, int attk,
    const float* __restrict__ bp, const float* __restrict__ q,
    float* __restrict__ wsum) {
    __shared__ uint32_t AS[2][2048];
    __shared__ uint32_t BS[2][2048];
    __shared__ float sb[6];

    const int tid = threadIdx.x;
    const int lane = tid & 31;
    const int wid = tid >> 5;
    const int warpM = wid & 3;
    const int warpN = wid >> 2;
    constexpr int NT = NOUT / 128;
    const int u = u0 + blockIdx.x / NT;
    const int bn = (blockIdx.x % NT) * 128;
    const int bm = blockIdx.y * 128;

    if (ATT && tid < 6) sb[tid] = 0.f;

    const int aoff = (CH ? (u >> 2) * 2 : 0) + ((u & 3) >> 1);
    const bf16* A1 = A1b + (size_t)aoff * M * KK;
    const bf16* A2 = A2b + (size_t)aoff * M * KK;
    const bf16* B1 = Bt1 + (size_t)u * KK * NOUT;
    const bf16* B2 = Bt2 + (size_t)u * KK * NOUT;
    float* Yp = Y + (size_t)u * M * NOUT;

    const bf16* APass[3] = {A1, A1, A2};
    const bf16* BPass[3] = {B1, B2, B1};

    constexpr int CPP = KK / 32;
    constexpr int NC = CHAINS * CPP;

    float c[2][8][4];
#pragma unroll
    for (int i = 0; i < 2; ++i)
#pragma unroll
        for (int j = 0; j < 8; ++j)
#pragma unroll
            for (int l = 0; l < 4; ++l) c[i][j][l] = 0.f;

    uint4 va[2], vb[2];
    {
        const bf16* Ag = APass[0];
        const bf16* Bg = BPass[0];
#pragma unroll
        for (int i = 0; i < 2; ++i) {
            int u2 = tid + i * 256;
            int m = u2 >> 2, seg = u2 & 3;
            int gm = bm + m;
            va[i] = make_uint4(0, 0, 0, 0);
            if (gm < M)
                va[i] = *(const uint4*)(Ag + (size_t)gm * KK + (seg >> 1) * 16 + (seg & 1) * 8);
            int n = u2 >> 2;
            vb[i] = *(const uint4*)(Bg + (size_t)(bn + n) * KK + (seg >> 1) * 16 + (seg & 1) * 8);
        }
    }

#pragma unroll 1
    for (int g = 0; g < NC; ++g) {
        const int buf = g & 1;
#pragma unroll
        for (int i = 0; i < 2; ++i) {
            int u2 = tid + i * 256;
            int m = u2 >> 2, seg = u2 & 3;
            int kb = seg >> 1, h = seg & 1;
            int r = ((m >> 3) & 1) + 2 * h;
            int Lb = (((m & 7) * 4) + seg * 8) & 31;
            int W = ((kb * 8 + (m >> 4)) * 4 + r) * 32 + Lb;
            *(uint4*)&AS[buf][W] = va[i];
            int n = m;
            int Wb = ((kb * 16 + (n >> 3)) * 2 + h) * 32 + Lb;
            *(uint4*)&BS[buf][Wb] = vb[i];
        }
        __syncthreads();

        if (g + 1 < NC) {
            int pass = (g + 1) / CPP, kc = (g + 1) % CPP;
            const bf16* Ag = APass[pass];
            const bf16* Bg = BPass[pass];
            int koff = kc * 32;
#pragma unroll
            for (int i = 0; i < 2; ++i) {
                int u2 = tid + i * 256;
                int m = u2 >> 2, seg = u2 & 3;
                int gm = bm + m;
                va[i] = make_uint4(0, 0, 0, 0);
                if (gm < M)
                    va[i] = *(const uint4*)(Ag + (size_t)gm * KK + koff +
                                            (seg >> 1) * 16 + (seg & 1) * 8);
                vb[i] = *(const uint4*)(Bg + (size_t)(bn + m) * KK + koff +
                                        (seg >> 1) * 16 + (seg & 1) * 8);
            }
        }

#pragma unroll
        for (int kb = 0; kb < 2; ++kb) {
            uint32_t a[2][4], b[8][2];
#pragma unroll
            for (int mbl = 0; mbl < 2; ++mbl) {
                int mb = warpM * 2 + mbl;
#pragma unroll
                for (int r = 0; r < 4; ++r) {
                    int Lr = (lane + (kb * 2 + (r >> 1)) * 8) & 31;
                    a[mbl][r] = AS[buf][((kb * 8 + mb) * 4 + r) * 32 + Lr];
                }
            }
#pragma unroll
            for (int nbl = 0; nbl < 8; ++nbl) {
                int nb = warpN * 8 + nbl;
#pragma unroll
                for (int h = 0; h < 2; ++h) {
                    int Lr = (lane + (kb * 2 + h) * 8) & 31;
                    b[nbl][h] = BS[buf][((kb * 16 + nb) * 2 + h) * 32 + Lr];
                }
            }
#pragma unroll
            for (int mbl = 0; mbl < 2; ++mbl)
#pragma unroll
                for (int nbl = 0; nbl < 8; ++nbl)
                    mma16816(c[mbl][nbl], a[mbl], b[nbl]);
        }
        __syncthreads();
    }

    if (ATT) {
        float s[2][2] = {{0.f, 0.f}, {0.f, 0.f}};
#pragma unroll
        for (int mbl = 0; mbl < 2; ++mbl)
#pragma unroll
            for (int nbl = 0; nbl < 8; ++nbl) {
                int ncol = warpN * 64 + nbl * 8 + (lane & 3) * 2;
                float bp0 = __ldg(bp + ncol), bp1 = __ldg(bp + ncol + 1);
                float q0 = __ldg(q + ncol), q1 = __ldg(q + ncol + 1);
                s[mbl][0] += tanhf(c[mbl][nbl][0] + bp0) * q0
                           + tanhf(c[mbl][nbl][1] + bp1) * q1;
                s[mbl][1] += tanhf(c[mbl][nbl][2] + bp0) * q0
                           + tanhf(c[mbl][nbl][3] + bp1) * q1;
            }
#pragma unroll
        for (int mbl = 0; mbl < 2; ++mbl)
#pragma unroll
            for (int h2 = 0; h2 < 2; ++h2) {
                float v = s[mbl][h2];
                v += __shfl_xor_sync(0xffffffffu, v, 1);
                v += __shfl_xor_sync(0xffffffffu, v, 2);
                if ((lane & 3) == 0) {
                    int grow = bm + warpM * 32 + mbl * 16 + h2 * 8 + (lane >> 2);
                    if (grow < M) {
                        int t = (grow >= NN) ? 1 : 0;
                        atomicAdd(&sb[t * 3 + attk], v);
                    }
                }
            }
        __syncthreads();
        if (tid < 6 && sb[tid] != 0.f) atomicAdd(&wsum[tid], sb[tid]);
    } else {
#pragma unroll
        for (int mbl = 0; mbl < 2; ++mbl) {
            int mrow = bm + warpM * 32 + mbl * 16 + (lane >> 2);
#pragma unroll
            for (int nbl = 0; nbl < 8; ++nbl) {
                int ncol = bn + warpN * 64 + nbl * 8 + (lane & 3) * 2;
                float* base = Yp + (size_t)mrow * NOUT + ncol;
                if (mrow < M)
                    *(float2*)base = make_float2(c[mbl][nbl][0], c[mbl][nbl][1]);
                if (mrow + 8 < M)
                    *(float2*)(base + (size_t)8 * NOUT) =
                        make_float2(c[mbl][nbl][2], c[mbl][nbl][3]);
            }
        }
    }
}

// --------- fused gather layer1 (one channel; blockIdx.y = type), 2x unroll ---------
__global__ void __launch_bounds__(256) k_gag1(
    const float* __restrict__ y,
    const int* __restrict__ csrs, const float* __restrict__ csrw,
    const int* __restrict__ base, const int* __restrict__ cnt,
    const float* __restrict__ rin, const float* __restrict__ b1,
    bf16* __restrict__ h1, bf16* __restrict__ h2, int ci) {
    int gw = (blockIdx.x * blockDim.x + threadIdx.x) >> 5;
    if (gw >= NN) return;
    int lane = threadIdx.x & 31;
    int d = gw;
    int t = blockIdx.y;
    int by = ci * 2 + t;
    int uLo = ci * 4 + t, uHi = uLo + 2;
    int c = (ci == 0) ? 0 : (ci == 1 ? 2 : 3);
    const float* yLo = y + (size_t)uLo * NN * HID_F;
    const float* yHi = y + (size_t)uHi * NN * HID_F;
    const float* bLo = b1 + (c * 4 + t) * HID_F;
    const float* bHi = b1 + (c * 4 + t + 2) * HID_F;

    float4 a0 = make_float4(0, 0, 0, 0), a1 = a0, e0 = a0, e1 = a0;
    float4 c0 = a0, c1 = a0, f0 = a0, f1 = a0;
    {
        int b = base[uLo * NN + d], n = cnt[uLo * NN + d];
        const int* cs = csrs + (size_t)uLo * EE;
        const float* cw = csrw + (size_t)uLo * EE;
        int i = 0;
        for (; i + 2 <= n; i += 2) {
            int s0 = cs[b + i], s1 = cs[b + i + 1];
            float w0 = cw[b + i], w1 = cw[b + i + 1];
            const float4* r0 = (const float4*)(yLo + (size_t)s0 * HID_F);
            const float4* r1 = (const float4*)(yLo + (size_t)s1 * HID_F);
            fma4(a0, w0, r0[lane]);
            fma4(a1, w0, r0[32 + lane]);
            fma4(e0, w1, r1[lane]);
            fma4(e1, w1, r1[32 + lane]);
        }
        if (i < n) {
            int s0 = cs[b + i];
            float w0 = cw[b + i];
            const float4* r0 = (const float4*)(yLo + (size_t)s0 * HID_F);
            fma4(a0, w0, r0[lane]);
            fma4(a1, w0, r0[32 + lane]);
        }
    }
    {
        int b = base[uHi * NN + d], n = cnt[uHi * NN + d];
        const int* cs = csrs + (size_t)uHi * EE;
        const float* cw = csrw + (size_t)uHi * EE;
        int i = 0;
        for (; i + 2 <= n; i += 2) {
            int s0 = cs[b + i], s1 = cs[b + i + 1];
            float w0 = cw[b + i], w1 = cw[b + i + 1];
            const float4* r0 = (const float4*)(yHi + (size_t)s0 * HID_F);
            const float4* r1 = (const float4*)(yHi + (size_t)s1 * HID_F);
            fma4(c0, w0, r0[lane]);
            fma4(c1, w0, r0[32 + lane]);
            fma4(f0, w1, r1[lane]);
            fma4(f1, w1, r1[32 + lane]);
        }
        if (i < n) {
            int s0 = cs[b + i];
            float w0 = cw[b + i];
            const float4* r0 = (const float4*)(yHi + (size_t)s0 * HID_F);
            fma4(c0, w0, r0[lane]);
            fma4(c1, w0, r0[32 + lane]);
        }
    }
    a0.x += e0.x; a0.y += e0.y; a0.z += e0.z; a0.w += e0.w;
    a1.x += e1.x; a1.y += e1.y; a1.z += e1.z; a1.w += e1.w;
    c0.x += f0.x; c0.y += f0.y; c0.z += f0.z; c0.w += f0.w;
    c1.x += f1.x; c1.y += f1.y; c1.z += f1.z; c1.w += f1.w;

    float rl = rin[uLo * NN + d], rh = rin[uHi * NN + d];
    bf16* o1 = h1 + (size_t)by * NN * HID_F;
    bf16* o2 = h2 + (size_t)by * NN * HID_F;
#pragma unroll
    for (int ch = 0; ch < 2; ++ch) {
        float4 A = ch ? a1 : a0, C = ch ? c1 : c0;
        float4 x = ((const float4*)bLo)[ch * 32 + lane];
        float4 yb = ((const float4*)bHi)[ch * 32 + lane];
        float r0 = fmaxf(x.x + yb.x + rl * A.x + rh * C.x, 0.f);
        float r1 = fmaxf(x.y + yb.y + rl * A.y + rh * C.y, 0.f);
        float r2 = fmaxf(x.z + yb.z + rl * A.z + rh * C.z, 0.f);
        float r3 = fmaxf(x.w + yb.w + rl * A.w + rh * C.w, 0.f);
        bf16 h0 = __float2bfloat16(r0), hh1 = __float2bfloat16(r1);
        bf16 h2v = __float2bfloat16(r2), h3 = __float2bfloat16(r3);
        __nv_bfloat162 p0 = __halves2bfloat162(h0, hh1);
        __nv_bfloat162 p1 = __halves2bfloat162(h2v, h3);
        uint2 st;
        st.x = *(unsigned*)&p0; st.y = *(unsigned*)&p1;
        size_t off = (size_t)d * HID_F + ch * 128 + lane * 4;
        *(uint2*)(o1 + off) = st;
        bf16 l0 = __float2bfloat16(r0 - __bfloat162float(h0));
        bf16 l1 = __float2bfloat16(r1 - __bfloat162float(hh1));
        bf16 l2 = __float2bfloat16(r2 - __bfloat162float(h2v));
        bf16 l3 = __float2bfloat16(r3 - __bfloat162float(h3));
        p0 = __halves2bfloat162(l0, l1);
        p1 = __halves2bfloat162(l2, l3);
        st.x = *(unsigned*)&p0; st.y = *(unsigned*)&p1;
        *(uint2*)(o2 + off) = st;
    }
}

// --------- fused gather layer2 + z hi-split (channel-contiguous za rows) ---------
__global__ void __launch_bounds__(256) k_gag2(
    const float* __restrict__ y2,
    const int* __restrict__ csrs, const float* __restrict__ csrw,
    const int* __restrict__ base, const int* __restrict__ cnt,
    const float* __restrict__ rin, const float* __restrict__ b2,
    float* __restrict__ zd, float* __restrict__ zp,
    bf16* __restrict__ za1, int ci) {
    int gw = (blockIdx.x * blockDim.x + threadIdx.x) >> 5;
    if (gw >= NN) return;
    int lane = threadIdx.x & 31;
    int d = gw;
    int t = blockIdx.y;
    int uLo = ci * 4 + t, uHi = uLo + 2;
    int c = (ci == 0) ? 0 : (ci == 1 ? 2 : 3);
    const float* yLo = y2 + (size_t)uLo * NN * OUT_F;
    const float* yHi = y2 + (size_t)uHi * NN * OUT_F;
    const float* bLo = b2 + (c * 4 + t) * OUT_F;
    const float* bHi = b2 + (c * 4 + t + 2) * OUT_F;

    float4 a0 = make_float4(0, 0, 0, 0), e0 = a0, c0 = a0, f0 = a0;
    {
        int b = base[uLo * NN + d], n = cnt[uLo * NN + d];
        const int* cs = csrs + (size_t)uLo * EE;
        const float* cw = csrw + (size_t)uLo * EE;
        int i = 0;
        for (; i + 2 <= n; i += 2) {
            fma4(a0, cw[b + i], ((const float4*)(yLo + (size_t)cs[b + i] * OUT_F))[lane]);
            fma4(e0, cw[b + i + 1],
                 ((const float4*)(yLo + (size_t)cs[b + i + 1] * OUT_F))[lane]);
        }
        if (i < n)
            fma4(a0, cw[b + i], ((const float4*)(yLo + (size_t)cs[b + i] * OUT_F))[lane]);
    }
    {
        int b = base[uHi * NN + d], n = cnt[uHi * NN + d];
        const int* cs = csrs + (size_t)uHi * EE;
        const float* cw = csrw + (size_t)uHi * EE;
        int i = 0;
        for (; i + 2 <= n; i += 2) {
            fma4(c0, cw[b + i], ((const float4*)(yHi + (size_t)cs[b + i] * OUT_F))[lane]);
            fma4(f0, cw[b + i + 1],
                 ((const float4*)(yHi + (size_t)cs[b + i + 1] * OUT_F))[lane]);
        }
        if (i < n)
            fma4(c0, cw[b + i], ((const float4*)(yHi + (size_t)cs[b + i] * OUT_F))[lane]);
    }
    a0.x += e0.x; a0.y += e0.y; a0.z += e0.z; a0.w += e0.w;
    c0.x += f0.x; c0.y += f0.y; c0.z += f0.z; c0.w += f0.w;

    float rl = rin[uLo * NN + d], rh = rin[uHi * NN + d];
    float4 x = ((const float4*)bLo)[lane], yb = ((const float4*)bHi)[lane];
    float4 res;
    res.x = fmaxf(x.x + yb.x + rl * a0.x + rh * c0.x, 0.f);
    res.y = fmaxf(x.y + yb.y + rl * a0.y + rh * c0.y, 0.f);
    res.z = fmaxf(x.z + yb.z + rl * a0.z + rh * c0.z, 0.f);
    res.w = fmaxf(x.w + yb.w + rl * a0.w + rh * c0.w, 0.f);
    float* zt = t ? zp : zd;
    *(float4*)(zt + (size_t)d * (3 * OUT_F) + ci * OUT_F + lane * 4) = res;

    size_t row = (size_t)ci * 2 * NN + (size_t)t * NN + d;
    bf16 h0 = __float2bfloat16(res.x), h1 = __float2bfloat16(res.y);
    bf16 h2 = __float2bfloat16(res.z), h3 = __float2bfloat16(res.w);
    __nv_bfloat162 p0 = __halves2bfloat162(h0, h1);
    __nv_bfloat162 p1 = __halves2bfloat162(h2, h3);
    uint2 st;
    st.x = *(unsigned*)&p0; st.y = *(unsigned*)&p1;
    *(uint2*)(za1 + row * OUT_F + lane * 4) = st;
}

// ------------- combine with fused beta (block-local softmax of wsum) -------------
__global__ void k_combine(const float* __restrict__ zd, const float* __restrict__ zp,
                          const float* __restrict__ wsum, float* __restrict__ out,
                          float* __restrict__ outBeta) {
    __shared__ float sb[6];
    if (threadIdx.x == 0) {
#pragma unroll
        for (int t = 0; t < 2; ++t) {
            float w0 = wsum[t * 3 + 0] / (float)NN;
            float w1 = wsum[t * 3 + 1] / (float)NN;
            float w2 = wsum[t * 3 + 2] / (float)NN;
            float m = fmaxf(w0, fmaxf(w1, w2));
            float e0 = expf(w0 - m), e1 = expf(w1 - m), e2 = expf(w2 - m);
            float inv = 1.f / (e0 + e1 + e2);
            sb[t * 3 + 0] = e0 * inv;
            sb[t * 3 + 1] = e1 * inv;
            sb[t * 3 + 2] = e2 * inv;
        }
    }
    __syncthreads();
    if (blockIdx.x == 0 && threadIdx.x < 6) outBeta[threadIdx.x] = sb[threadIdx.x];
    int i = blockIdx.x * blockDim.x + threadIdx.x;
    if (i >= 2 * NN * OUT_F) return;
    int t = i / (NN * OUT_F);
    int r = i - t * NN * OUT_F;
    int n = r / OUT_F, f = r - n * OUT_F;
    const float* z = (t ? zp : zd) + (size_t)n * (3 * OUT_F) + f;
    out[i] = sb[t * 3 + 0] * z[0] + sb[t * 3 + 1] * z[OUT_F] + sb[t * 3 + 2] * z[2 * OUT_F];
}

// ---------------- host orchestration ----------------
extern "C" void kernel_launch(void* const* d_in, const int* in_sizes, int n_in,
                              void* d_out, int out_size) {
    const float* xd  = (const float*)d_in[0];
    const float* xp  = (const float*)d_in[1];
    const int*   src = (const int*)  d_in[2];
    const int*   dst = (const int*)  d_in[3];
    const float* W1  = (const float*)d_in[4];
    const float* b1  = (const float*)d_in[5];
    const float* W2  = (const float*)d_in[6];
    const float* b2  = (const float*)d_in[7];
    const float* Wpm = (const float*)d_in[8];
    const float* bp  = (const float*)d_in[9];
    const float* q   = (const float*)d_in[10];
    float* out = (float*)d_out;

    float *y, *y2, *zd, *zp, *rout, *rin, *wsum, *csrw;
    int *cnts, *cnt, *base, *cur, *csrs;
    bf16 *x1, *x2, *h1, *h2, *za1;
    bf16 *wt1a, *wt1b, *wt2a, *wt2b, *wpa, *wpb;
    cudaGetSymbolAddress((void**)&y,    g_y);
    cudaGetSymbolAddress((void**)&y2,   g_y2);
    cudaGetSymbolAddress((void**)&zd,   g_zd);
    cudaGetSymbolAddress((void**)&zp,   g_zp);
    cudaGetSymbolAddress((void**)&rout, g_rout);
    cudaGetSymbolAddress((void**)&rin,  g_rin);
    cudaGetSymbolAddress((void**)&wsum, g_wsum);
    cudaGetSymbolAddress((void**)&cnts, g_cnts);
    cudaGetSymbolAddress((void**)&cnt,  g_cnt);
    cudaGetSymbolAddress((void**)&base, g_base);
    cudaGetSymbolAddress((void**)&cur,  g_cur);
    cudaGetSymbolAddress((void**)&csrs, g_csrs);
    cudaGetSymbolAddress((void**)&csrw, g_csrw);
    cudaGetSymbolAddress((void**)&x1,   g_x1);
    cudaGetSymbolAddress((void**)&x2,   g_x2);
    cudaGetSymbolAddress((void**)&h1,   g_h1);
    cudaGetSymbolAddress((void**)&h2,   g_h2);
    cudaGetSymbolAddress((void**)&za1,  g_za1);
    cudaGetSymbolAddress((void**)&wt1a, g_wt1a);
    cudaGetSymbolAddress((void**)&wt1b, g_wt1b);
    cudaGetSymbolAddress((void**)&wt2a, g_wt2a);
    cudaGetSymbolAddress((void**)&wt2b, g_wt2b);
    cudaGetSymbolAddress((void**)&wpa,  g_wpa);
    cudaGetSymbolAddress((void**)&wpb,  g_wpb);

    const int T = 256;
    const int mtiles = (NN + 127) / 128;            // 235
    const int gblocks = (NN * 32 + T - 1) / T;      // 3750
    cudaStream_t sd = g_ss.side;

    cudaEventRecord(g_ss.fork, 0);
    cudaStreamWaitEvent(sd, g_ss.fork, 0);
    cudaStreamWaitEvent(g_ss.sc[0], g_ss.fork, 0);

    // kernel #1: split xd (main)
    k_split<<<(NN * IN_F / 4 + T - 1) / T, T>>>(xd, x1, x2, NN * IN_F / 4);
    // kernel #2: split xp (channel stream 0)
    k_split<<<(NN * IN_F / 4 + T - 1) / T, T, 0, g_ss.sc[0]>>>(
        xp, x1 + (size_t)NN * IN_F, x2 + (size_t)NN * IN_F, NN * IN_F / 4);
    cudaEventRecord(g_ss.xe, g_ss.sc[0]);
    // kernel #3: W1 transform (side)
    k_wts<<<dim3(HID_F / 32, IN_F / 32, 12), dim3(32, 8), 0, sd>>>(W1, wt1a, wt1b, IN_F, HID_F);
    cudaEventRecord(g_ss.w1e, sd);

    // kernel #4: GEMM1 channel 0 (ncu -s 5 -c 1 lands here)
    cudaStreamWaitEvent(0, g_ss.w1e, 0);
    cudaStreamWaitEvent(0, g_ss.xe, 0);
    k_mma<IN_F, HID_F, 0, 3, 0><<<dim3(4 * (HID_F / 128), mtiles), 256>>>(
        x1, x2, wt1a, wt1b, y, NN, 0, 0, nullptr, nullptr, nullptr);
    cudaEventRecord(g_ss.e1[0], 0);

    // side chain: CSR build + remaining weight transforms + wsum zero
    k_zeroi2<<<(12 * NN + T - 1) / T, T, 0, sd>>>(cnts, cnt, 12 * NN);
    k_hist2<<<(12 * EE + T - 1) / T, T, 0, sd>>>(src, dst, cnts, cnt);
    k_prep<<<(12 * NN + T - 1) / T, T, 0, sd>>>(cnts, cnt, rout, rin);
    k_scan<<<12, 1024, 0, sd>>>(cnt, base, cur);
    k_fill<<<(12 * EE + T - 1) / T, T, 0, sd>>>(src, dst, rout, cur, csrs, csrw);
    k_wts<<<dim3(OUT_F / 32, HID_F / 32, 12), dim3(32, 8), 0, sd>>>(W2, wt2a, wt2b, HID_F, OUT_F);
    k_wts1<<<dim3(OUT_F / 32, OUT_F / 32), dim3(32, 8), 0, sd>>>(Wpm, wpa, wpb, OUT_F, OUT_F);
    k_zero<<<1, 32, 0, sd>>>(wsum, 8);
    cudaEventRecord(g_ss.join, sd);

    // GEMM1 channels 1,2 (main)
    for (int c = 1; c < 3; ++c) {
        k_mma<IN_F, HID_F, 0, 3, 0><<<dim3(4 * (HID_F / 128), mtiles), 256>>>(
            x1, x2, wt1a, wt1b, y, NN, c * 4, 0, nullptr, nullptr, nullptr);
        cudaEventRecord(g_ss.e1[c], 0);
    }

    // per-channel pipelines: gag1 -> GEMM2 -> gag2 -> attention GEMM
    for (int c = 0; c < 3; ++c) {
        cudaStream_t s = g_ss.sc[c];
        cudaStreamWaitEvent(s, g_ss.e1[c], 0);
        cudaStreamWaitEvent(s, g_ss.join, 0);
        k_gag1<<<dim3(gblocks, 2), T, 0, s>>>(y, csrs, csrw, base, cnt, rin, b1,
                                              h1, h2, c);
        k_mma<HID_F, OUT_F, 1, 3, 0><<<dim3(4, mtiles), 256, 0, s>>>(
            h1, h2, wt2a, wt2b, y2, NN, c * 4, 0, nullptr, nullptr, nullptr);
        k_gag2<<<dim3(gblocks, 2), T, 0, s>>>(y2, csrs, csrw, base, cnt, rin, b2,
                                              zd, zp, za1, c);
        k_mma<OUT_F, OUT_F, 0, 2, 1><<<dim3(1, (2 * NN + 127) / 128), 256, 0, s>>>(
            za1 + (size_t)c * 2 * NN * OUT_F, za1 + (size_t)c * 2 * NN * OUT_F,
            wpa, wpb, nullptr, 2 * NN, 0, c, bp, q, wsum);
        cudaEventRecord(g_ss.ec[c], s);
    }

    // join all channels, then fused beta+combine on main
    for (int c = 0; c < 3; ++c) cudaStreamWaitEvent(0, g_ss.ec[c], 0);
    k_combine<<<(2 * NN * OUT_F + T - 1) / T, T>>>(zd, zp, wsum, out,
                                                   out + (size_t)2 * NN * OUT_F);
}

// round 14
// speedup vs baseline: 1.2904x; 1.2904x over previous
#include <cuda_runtime.h>
#include <cuda_fp16.h>
#include <cstdint>

#define NN 30000
#define EE 250000
#define IN_F 512
#define HID_F 256
#define OUT_F 128

typedef unsigned long long u64;
typedef __half fp16;

// ---------------- scratch (static device globals; no allocs) ----------------
__device__ float g_y[(size_t)12 * NN * HID_F];
__device__ float g_y2[(size_t)12 * NN * OUT_F];
__device__ float g_zd[(size_t)NN * 3 * OUT_F];
__device__ float g_zp[(size_t)NN * 3 * OUT_F];
__device__ float g_rout[12 * NN];
__device__ float g_rin[12 * NN];
__device__ float g_wsum[8];
__device__ int   g_cnts[12 * NN];
__device__ int   g_cnt[12 * NN];
__device__ int   g_base[12 * NN];
__device__ int   g_cur[12 * NN];
__device__ int   g_csrs[(size_t)12 * EE];
__device__ float g_csrw[(size_t)12 * EE];
__device__ __align__(16) fp16 g_x1[(size_t)2 * NN * IN_F];
__device__ __align__(16) fp16 g_h1[(size_t)6 * NN * HID_F];
__device__ __align__(16) fp16 g_za1[(size_t)2 * NN * 3 * OUT_F];
__device__ __align__(16) fp16 g_wt1a[(size_t)12 * HID_F * IN_F];
__device__ __align__(16) fp16 g_wt1b[(size_t)12 * HID_F * IN_F];
__device__ __align__(16) fp16 g_wt2a[(size_t)12 * OUT_F * HID_F];
__device__ __align__(16) fp16 g_wt2b[(size_t)12 * OUT_F * HID_F];
__device__ __align__(16) fp16 g_wpa[(size_t)OUT_F * OUT_F];
__device__ __align__(16) fp16 g_wpb[(size_t)OUT_F * OUT_F];

__device__ __forceinline__ void fma4(float4& a, float w, const float4 v) {
    a.x += w * v.x; a.y += w * v.y; a.z += w * v.z; a.w += w * v.w;
}
__device__ __forceinline__ int u2cr(int u) {
    int ci = u >> 2;
    int c = (ci == 0) ? 0 : (ci == 1 ? 2 : 3);
    return c * 4 + (u & 3);
}

// ---------------- stream handles (created at static init, pre-checkpoint) ----
struct Streams {
    cudaStream_t side = nullptr;
    cudaStream_t sc[3] = {nullptr, nullptr, nullptr};
    cudaEvent_t fork = nullptr, join = nullptr, w1e = nullptr, xe = nullptr;
    cudaEvent_t e1[3] = {nullptr, nullptr, nullptr};
    cudaEvent_t ec[3] = {nullptr, nullptr, nullptr};
    Streams() {
        cudaStreamCreateWithFlags(&side, cudaStreamNonBlocking);
        cudaEventCreateWithFlags(&fork, cudaEventDisableTiming);
        cudaEventCreateWithFlags(&join, cudaEventDisableTiming);
        cudaEventCreateWithFlags(&w1e, cudaEventDisableTiming);
        cudaEventCreateWithFlags(&xe, cudaEventDisableTiming);
        for (int c = 0; c < 3; ++c) {
            cudaStreamCreateWithFlags(&sc[c], cudaStreamNonBlocking);
            cudaEventCreateWithFlags(&e1[c], cudaEventDisableTiming);
            cudaEventCreateWithFlags(&ec[c], cudaEventDisableTiming);
        }
    }
};
static Streams g_ss;

// ---------------- utility kernels ----------------
__global__ void k_zero(float* __restrict__ p, int n) {
    int i = blockIdx.x * blockDim.x + threadIdx.x;
    if (i < n) p[i] = 0.f;
}
__global__ void k_zeroi2(int* __restrict__ a, int* __restrict__ b, int n) {
    int i = blockIdx.x * blockDim.x + threadIdx.x;
    if (i < n) { a[i] = 0; b[i] = 0; }
}

__global__ void k_hist2(const int* __restrict__ src, const int* __restrict__ dst,
                        int* __restrict__ cnts, int* __restrict__ cntd) {
    int i = blockIdx.x * blockDim.x + threadIdx.x;
    if (i >= 12 * EE) return;
    int u = i / EE, e = i - u * EE;
    int cr = u2cr(u);
    atomicAdd(&cnts[u * NN + src[(size_t)cr * EE + e]], 1);
    atomicAdd(&cntd[u * NN + dst[(size_t)cr * EE + e]], 1);
}

__global__ void k_prep(const int* __restrict__ cnts, const int* __restrict__ cntd,
                       float* __restrict__ rout, float* __restrict__ rin) {
    int i = blockIdx.x * blockDim.x + threadIdx.x;
    if (i >= 12 * NN) return;
    rout[i] = rsqrtf((float)max(cnts[i], 1));
    rin[i]  = rsqrtf((float)max(cntd[i], 1));
}

// deterministic exclusive scan per u (12 blocks, 1024 threads)
__global__ void k_scan(const int* __restrict__ cnt, int* __restrict__ base,
                       int* __restrict__ cur) {
    __shared__ int ws[32];
    __shared__ int carry;
    int u = blockIdx.x;
    const int* c = cnt + u * NN;
    int* b = base + u * NN;
    int* q = cur + u * NN;
    int lane = threadIdx.x & 31, w = threadIdx.x >> 5;
    if (threadIdx.x == 0) carry = 0;
    __syncthreads();
    for (int off = 0; off < NN; off += 1024) {
        int i = off + threadIdx.x;
        int v = (i < NN) ? c[i] : 0;
        int s = v;
#pragma unroll
        for (int o = 1; o < 32; o <<= 1) {
            int t = __shfl_up_sync(0xffffffffu, s, o);
            if (lane >= o) s += t;
        }
        if (lane == 31) ws[w] = s;
        __syncthreads();
        if (w == 0) {
            int t2 = ws[lane];
#pragma unroll
            for (int o = 1; o < 32; o <<= 1) {
                int t = __shfl_up_sync(0xffffffffu, t2, o);
                if (lane >= o) t2 += t;
            }
            ws[lane] = t2;
        }
        __syncthreads();
        int excl = s - v + (w > 0 ? ws[w - 1] : 0) + carry;
        if (i < NN) { b[i] = excl; q[i] = excl; }
        __syncthreads();
        if (threadIdx.x == 1023) carry = excl + v;
        __syncthreads();
    }
}

__global__ void k_fill(const int* __restrict__ src, const int* __restrict__ dst,
                       const float* __restrict__ rout, int* __restrict__ cur,
                       int* __restrict__ csrs, float* __restrict__ csrw) {
    int i = blockIdx.x * blockDim.x + threadIdx.x;
    if (i >= 12 * EE) return;
    int u = i / EE, e = i - u * EE;
    int cr = u2cr(u);
    int s = src[(size_t)cr * EE + e];
    int d = dst[(size_t)cr * EE + e];
    int pos = atomicAdd(&cur[u * NN + d], 1);
    csrs[(size_t)u * EE + pos] = s;
    csrw[(size_t)u * EE + pos] = rout[u * NN + s];
}

// fp32 -> fp16 (hi only; activations are single-operand in the 2-chain scheme)
__global__ void k_half(const float* __restrict__ x, fp16* __restrict__ hi, int n4) {
    int i = blockIdx.x * blockDim.x + threadIdx.x;
    if (i >= n4) return;
    float4 v = ((const float4*)x)[i];
    ((__half2*)hi)[2 * i]     = __floats2half2_rn(v.x, v.y);
    ((__half2*)hi)[2 * i + 1] = __floats2half2_rn(v.z, v.w);
}

// transpose+split weights: W [16][K][N] fp32 (channels 0,2,3) -> [12][N][K] fp16 hi/lo
__global__ void k_wts(const float* __restrict__ W, fp16* __restrict__ t1,
                      fp16* __restrict__ t2, int K, int N) {
    __shared__ float tile[32][33];
    int z = blockIdx.z;
    int cz = z >> 2;
    int c = (cz == 0) ? 0 : (cz == 1 ? 2 : 3);
    const float* Wm = W + (size_t)(c * 4 + (z & 3)) * K * N;
    fp16* o1 = t1 + (size_t)z * K * N;
    fp16* o2 = t2 + (size_t)z * K * N;
    int k0 = blockIdx.y * 32, n0 = blockIdx.x * 32;
    for (int r = threadIdx.y; r < 32; r += 8)
        tile[r][threadIdx.x] = Wm[(size_t)(k0 + r) * N + n0 + threadIdx.x];
    __syncthreads();
    for (int r = threadIdx.y; r < 32; r += 8) {
        float v = tile[threadIdx.x][r];
        fp16 h = __float2half_rn(v);
        size_t o = (size_t)(n0 + r) * K + k0 + threadIdx.x;
        o1[o] = h;
        o2[o] = __float2half_rn(v - __half2float(h));
    }
}

__global__ void k_wts1(const float* __restrict__ W, fp16* __restrict__ t1,
                       fp16* __restrict__ t2, int K, int N) {
    __shared__ float tile[32][33];
    int k0 = blockIdx.y * 32, n0 = blockIdx.x * 32;
    for (int r = threadIdx.y; r < 32; r += 8)
        tile[r][threadIdx.x] = W[(size_t)(k0 + r) * N + n0 + threadIdx.x];
    __syncthreads();
    for (int r = threadIdx.y; r < 32; r += 8) {
        float v = tile[threadIdx.x][r];
        fp16 h = __float2half_rn(v);
        size_t o = (size_t)(n0 + r) * K + k0 + threadIdx.x;
        t1[o] = h;
        t2[o] = __float2half_rn(v - __half2float(h));
    }
}

// ---------------- mma.sync fp16 GEMM, 128x128 tile (R6 winner struct) ----------------
// 2-chain: y = A1*B1 + A1*B2 (weights exact via hi+lo, activations single fp16).
__device__ __forceinline__ void mma16816(float* c, const uint32_t* a, const uint32_t* b) {
    asm volatile("mma.sync.aligned.m16n8k16.row.col.f32.f16.f16.f32 "
                 "{%0,%1,%2,%3}, {%4,%5,%6,%7}, {%8,%9}, {%0,%1,%2,%3};"
                 : "+f"(c[0]), "+f"(c[1]), "+f"(c[2]), "+f"(c[3])
                 : "r"(a[0]), "r"(a[1]), "r"(a[2]), "r"(a[3]), "r"(b[0]), "r"(b[1]));
}

template <int KK, int NOUT, int CH, int ATT>
__global__ void __launch_bounds__(256, 2) k_mma(
    const fp16* __restrict__ A1b,
    const fp16* __restrict__ Bt1, const fp16* __restrict__ Bt2,
    float* __restrict__ Y, int M, int u0, int attk,
    const float* __restrict__ bp, const float* __restrict__ q,
    float* __restrict__ wsum) {
    __shared__ uint32_t AS[2][2048];
    __shared__ uint32_t BS[2][2048];
    __shared__ float sb[6];

    const int tid = threadIdx.x;
    const int lane = tid & 31;
    const int wid = tid >> 5;
    const int warpM = wid & 3;
    const int warpN = wid >> 2;
    constexpr int NT = NOUT / 128;
    const int u = u0 + blockIdx.x / NT;
    const int bn = (blockIdx.x % NT) * 128;
    const int bm = blockIdx.y * 128;

    if (ATT && tid < 6) sb[tid] = 0.f;

    const int aoff = (CH ? (u >> 2) * 2 : 0) + ((u & 3) >> 1);
    const fp16* A1 = A1b + (size_t)aoff * M * KK;
    const fp16* B1 = Bt1 + (size_t)u * KK * NOUT;
    const fp16* B2 = Bt2 + (size_t)u * KK * NOUT;
    float* Yp = Y + (size_t)u * M * NOUT;

    const fp16* BPass[2] = {B1, B2};

    constexpr int CPP = KK / 32;
    constexpr int NC = 2 * CPP;

    float c[2][8][4];
#pragma unroll
    for (int i = 0; i < 2; ++i)
#pragma unroll
        for (int j = 0; j < 8; ++j)
#pragma unroll
            for (int l = 0; l < 4; ++l) c[i][j][l] = 0.f;

    uint4 va[2], vb[2];
    {
#pragma unroll
        for (int i = 0; i < 2; ++i) {
            int u2 = tid + i * 256;
            int m = u2 >> 2, seg = u2 & 3;
            int gm = bm + m;
            va[i] = make_uint4(0, 0, 0, 0);
            if (gm < M)
                va[i] = *(const uint4*)(A1 + (size_t)gm * KK + (seg >> 1) * 16 + (seg & 1) * 8);
            vb[i] = *(const uint4*)(B1 + (size_t)(bn + m) * KK + (seg >> 1) * 16 + (seg & 1) * 8);
        }
    }

#pragma unroll 1
    for (int g = 0; g < NC; ++g) {
        const int buf = g & 1;
#pragma unroll
        for (int i = 0; i < 2; ++i) {
            int u2 = tid + i * 256;
            int m = u2 >> 2, seg = u2 & 3;
            int kb = seg >> 1, h = seg & 1;
            int r = ((m >> 3) & 1) + 2 * h;
            int Lb = (((m & 7) * 4) + seg * 8) & 31;
            int W = ((kb * 8 + (m >> 4)) * 4 + r) * 32 + Lb;
            *(uint4*)&AS[buf][W] = va[i];
            int n = m;
            int Wb = ((kb * 16 + (n >> 3)) * 2 + h) * 32 + Lb;
            *(uint4*)&BS[buf][Wb] = vb[i];
        }
        __syncthreads();

        if (g + 1 < NC) {
            int pass = (g + 1) / CPP, kc = (g + 1) % CPP;
            const fp16* Bg = BPass[pass];
            int koff = kc * 32;
#pragma unroll
            for (int i = 0; i < 2; ++i) {
                int u2 = tid + i * 256;
                int m = u2 >> 2, seg = u2 & 3;
                int gm = bm + m;
                va[i] = make_uint4(0, 0, 0, 0);
                if (gm < M)
                    va[i] = *(const uint4*)(A1 + (size_t)gm * KK + koff +
                                            (seg >> 1) * 16 + (seg & 1) * 8);
                vb[i] = *(const uint4*)(Bg + (size_t)(bn + m) * KK + koff +
                                        (seg >> 1) * 16 + (seg & 1) * 8);
            }
        }

#pragma unroll
        for (int kb = 0; kb < 2; ++kb) {
            uint32_t a[2][4], b[8][2];
#pragma unroll
            for (int mbl = 0; mbl < 2; ++mbl) {
                int mb = warpM * 2 + mbl;
#pragma unroll
                for (int r = 0; r < 4; ++r) {
                    int Lr = (lane + (kb * 2 + (r >> 1)) * 8) & 31;
                    a[mbl][r] = AS[buf][((kb * 8 + mb) * 4 + r) * 32 + Lr];
                }
            }
#pragma unroll
            for (int nbl = 0; nbl < 8; ++nbl) {
                int nb = warpN * 8 + nbl;
#pragma unroll
                for (int h = 0; h < 2; ++h) {
                    int Lr = (lane + (kb * 2 + h) * 8) & 31;
                    b[nbl][h] = BS[buf][((kb * 16 + nb) * 2 + h) * 32 + Lr];
                }
            }
#pragma unroll
            for (int mbl = 0; mbl < 2; ++mbl)
#pragma unroll
                for (int nbl = 0; nbl < 8; ++nbl)
                    mma16816(c[mbl][nbl], a[mbl], b[nbl]);
        }
        __syncthreads();
    }

    if (ATT) {
        float s[2][2] = {{0.f, 0.f}, {0.f, 0.f}};
#pragma unroll
        for (int mbl = 0; mbl < 2; ++mbl)
#pragma unroll
            for (int nbl = 0; nbl < 8; ++nbl) {
                int ncol = warpN * 64 + nbl * 8 + (lane & 3) * 2;
                float bp0 = __ldg(bp + ncol), bp1 = __ldg(bp + ncol + 1);
                float q0 = __ldg(q + ncol), q1 = __ldg(q + ncol + 1);
                s[mbl][0] += tanhf(c[mbl][nbl][0] + bp0) * q0
                           + tanhf(c[mbl][nbl][1] + bp1) * q1;
                s[mbl][1] += tanhf(c[mbl][nbl][2] + bp0) * q0
                           + tanhf(c[mbl][nbl][3] + bp1) * q1;
            }
#pragma unroll
        for (int mbl = 0; mbl < 2; ++mbl)
#pragma unroll
            for (int h2 = 0; h2 < 2; ++h2) {
                float v = s[mbl][h2];
                v += __shfl_xor_sync(0xffffffffu, v, 1);
                v += __shfl_xor_sync(0xffffffffu, v, 2);
                if ((lane & 3) == 0) {
                    int grow = bm + warpM * 32 + mbl * 16 + h2 * 8 + (lane >> 2);
                    if (grow < M) {
                        int t = (grow >= NN) ? 1 : 0;
                        atomicAdd(&sb[t * 3 + attk], v);
                    }
                }
            }
        __syncthreads();
        if (tid < 6 && sb[tid] != 0.f) atomicAdd(&wsum[tid], sb[tid]);
    } else {
#pragma unroll
        for (int mbl = 0; mbl < 2; ++mbl) {
            int mrow = bm + warpM * 32 + mbl * 16 + (lane >> 2);
#pragma unroll
            for (int nbl = 0; nbl < 8; ++nbl) {
                int ncol = bn + warpN * 64 + nbl * 8 + (lane & 3) * 2;
                float* base = Yp + (size_t)mrow * NOUT + ncol;
                if (mrow < M)
                    *(float2*)base = make_float2(c[mbl][nbl][0], c[mbl][nbl][1]);
                if (mrow + 8 < M)
                    *(float2*)(base + (size_t)8 * NOUT) =
                        make_float2(c[mbl][nbl][2], c[mbl][nbl][3]);
            }
        }
    }
}

// --------- fused gather layer1 (one channel; blockIdx.y = type), 2x unroll ---------
__global__ void __launch_bounds__(256) k_gag1(
    const float* __restrict__ y,
    const int* __restrict__ csrs, const float* __restrict__ csrw,
    const int* __restrict__ base, const int* __restrict__ cnt,
    const float* __restrict__ rin, const float* __restrict__ b1,
    fp16* __restrict__ h1, int ci) {
    int gw = (blockIdx.x * blockDim.x + threadIdx.x) >> 5;
    if (gw >= NN) return;
    int lane = threadIdx.x & 31;
    int d = gw;
    int t = blockIdx.y;
    int by = ci * 2 + t;
    int uLo = ci * 4 + t, uHi = uLo + 2;
    int c = (ci == 0) ? 0 : (ci == 1 ? 2 : 3);
    const float* yLo = y + (size_t)uLo * NN * HID_F;
    const float* yHi = y + (size_t)uHi * NN * HID_F;
    const float* bLo = b1 + (c * 4 + t) * HID_F;
    const float* bHi = b1 + (c * 4 + t + 2) * HID_F;

    float4 a0 = make_float4(0, 0, 0, 0), a1 = a0, e0 = a0, e1 = a0;
    float4 c0 = a0, c1 = a0, f0 = a0, f1 = a0;
    {
        int b = base[uLo * NN + d], n = cnt[uLo * NN + d];
        const int* cs = csrs + (size_t)uLo * EE;
        const float* cw = csrw + (size_t)uLo * EE;
        int i = 0;
        for (; i + 2 <= n; i += 2) {
            int s0 = cs[b + i], s1 = cs[b + i + 1];
            float w0 = cw[b + i], w1 = cw[b + i + 1];
            const float4* r0 = (const float4*)(yLo + (size_t)s0 * HID_F);
            const float4* r1 = (const float4*)(yLo + (size_t)s1 * HID_F);
            fma4(a0, w0, r0[lane]);
            fma4(a1, w0, r0[32 + lane]);
            fma4(e0, w1, r1[lane]);
            fma4(e1, w1, r1[32 + lane]);
        }
        if (i < n) {
            int s0 = cs[b + i];
            float w0 = cw[b + i];
            const float4* r0 = (const float4*)(yLo + (size_t)s0 * HID_F);
            fma4(a0, w0, r0[lane]);
            fma4(a1, w0, r0[32 + lane]);
        }
    }
    {
        int b = base[uHi * NN + d], n = cnt[uHi * NN + d];
        const int* cs = csrs + (size_t)uHi * EE;
        const float* cw = csrw + (size_t)uHi * EE;
        int i = 0;
        for (; i + 2 <= n; i += 2) {
            int s0 = cs[b + i], s1 = cs[b + i + 1];
            float w0 = cw[b + i], w1 = cw[b + i + 1];
            const float4* r0 = (const float4*)(yHi + (size_t)s0 * HID_F);
            const float4* r1 = (const float4*)(yHi + (size_t)s1 * HID_F);
            fma4(c0, w0, r0[lane]);
            fma4(c1, w0, r0[32 + lane]);
            fma4(f0, w1, r1[lane]);
            fma4(f1, w1, r1[32 + lane]);
        }
        if (i < n) {
            int s0 = cs[b + i];
            float w0 = cw[b + i];
            const float4* r0 = (const float4*)(yHi + (size_t)s0 * HID_F);
            fma4(c0, w0, r0[lane]);
            fma4(c1, w0, r0[32 + lane]);
        }
    }
    a0.x += e0.x; a0.y += e0.y; a0.z += e0.z; a0.w += e0.w;
    a1.x += e1.x; a1.y += e1.y; a1.z += e1.z; a1.w += e1.w;
    c0.x += f0.x; c0.y += f0.y; c0.z += f0.z; c0.w += f0.w;
    c1.x += f1.x; c1.y += f1.y; c1.z += f1.z; c1.w += f1.w;

    float rl = rin[uLo * NN + d], rh = rin[uHi * NN + d];
    fp16* o1 = h1 + (size_t)by * NN * HID_F;
#pragma unroll
    for (int ch = 0; ch < 2; ++ch) {
        float4 A = ch ? a1 : a0, C = ch ? c1 : c0;
        float4 x = ((const float4*)bLo)[ch * 32 + lane];
        float4 yb = ((const float4*)bHi)[ch * 32 + lane];
        float r0 = fmaxf(x.x + yb.x + rl * A.x + rh * C.x, 0.f);
        float r1 = fmaxf(x.y + yb.y + rl * A.y + rh * C.y, 0.f);
        float r2 = fmaxf(x.z + yb.z + rl * A.z + rh * C.z, 0.f);
        float r3 = fmaxf(x.w + yb.w + rl * A.w + rh * C.w, 0.f);
        __half2 p0 = __floats2half2_rn(r0, r1);
        __half2 p1 = __floats2half2_rn(r2, r3);
        uint2 st;
        st.x = *(unsigned*)&p0; st.y = *(unsigned*)&p1;
        size_t off = (size_t)d * HID_F + ch * 128 + lane * 4;
        *(uint2*)(o1 + off) = st;
    }
}

// --------- fused gather layer2 + z fp16 (channel-contiguous za rows) ---------
__global__ void __launch_bounds__(256) k_gag2(
    const float* __restrict__ y2,
    const int* __restrict__ csrs, const float* __restrict__ csrw,
    const int* __restrict__ base, const int* __restrict__ cnt,
    const float* __restrict__ rin, const float* __restrict__ b2,
    float* __restrict__ zd, float* __restrict__ zp,
    fp16* __restrict__ za1, int ci) {
    int gw = (blockIdx.x * blockDim.x + threadIdx.x) >> 5;
    if (gw >= NN) return;
    int lane = threadIdx.x & 31;
    int d = gw;
    int t = blockIdx.y;
    int uLo = ci * 4 + t, uHi = uLo + 2;
    int c = (ci == 0) ? 0 : (ci == 1 ? 2 : 3);
    const float* yLo = y2 + (size_t)uLo * NN * OUT_F;
    const float* yHi = y2 + (size_t)uHi * NN * OUT_F;
    const float* bLo = b2 + (c * 4 + t) * OUT_F;
    const float* bHi = b2 + (c * 4 + t + 2) * OUT_F;

    float4 a0 = make_float4(0, 0, 0, 0), e0 = a0, c0 = a0, f0 = a0;
    {
        int b = base[uLo * NN + d], n = cnt[uLo * NN + d];
        const int* cs = csrs + (size_t)uLo * EE;
        const float* cw = csrw + (size_t)uLo * EE;
        int i = 0;
        for (; i + 2 <= n; i += 2) {
            fma4(a0, cw[b + i], ((const float4*)(yLo + (size_t)cs[b + i] * OUT_F))[lane]);
            fma4(e0, cw[b + i + 1],
                 ((const float4*)(yLo + (size_t)cs[b + i + 1] * OUT_F))[lane]);
        }
        if (i < n)
            fma4(a0, cw[b + i], ((const float4*)(yLo + (size_t)cs[b + i] * OUT_F))[lane]);
    }
    {
        int b = base[uHi * NN + d], n = cnt[uHi * NN + d];
        const int* cs = csrs + (size_t)uHi * EE;
        const float* cw = csrw + (size_t)uHi * EE;
        int i = 0;
        for (; i + 2 <= n; i += 2) {
            fma4(c0, cw[b + i], ((const float4*)(yHi + (size_t)cs[b + i] * OUT_F))[lane]);
            fma4(f0, cw[b + i + 1],
                 ((const float4*)(yHi + (size_t)cs[b + i + 1] * OUT_F))[lane]);
        }
        if (i < n)
            fma4(c0, cw[b + i], ((const float4*)(yHi + (size_t)cs[b + i] * OUT_F))[lane]);
    }
    a0.x += e0.x; a0.y += e0.y; a0.z += e0.z; a0.w += e0.w;
    c0.x += f0.x; c0.y += f0.y; c0.z += f0.z; c0.w += f0.w;

    float rl = rin[uLo * NN + d], rh = rin[uHi * NN + d];
    float4 x = ((const float4*)bLo)[lane], yb = ((const float4*)bHi)[lane];
    float4 res;
    res.x = fmaxf(x.x + yb.x + rl * a0.x + rh * c0.x, 0.f);
    res.y = fmaxf(x.y + yb.y + rl * a0.y + rh * c0.y, 0.f);
    res.z = fmaxf(x.z + yb.z + rl * a0.z + rh * c0.z, 0.f);
    res.w = fmaxf(x.w + yb.w + rl * a0.w + rh * c0.w, 0.f);
    float* zt = t ? zp : zd;
    *(float4*)(zt + (size_t)d * (3 * OUT_F) + ci * OUT_F + lane * 4) = res;

    size_t row = (size_t)ci * 2 * NN + (size_t)t * NN + d;
    __half2 p0 = __floats2half2_rn(res.x, res.y);
    __half2 p1 = __floats2half2_rn(res.z, res.w);
    uint2 st;
    st.x = *(unsigned*)&p0; st.y = *(unsigned*)&p1;
    *(uint2*)(za1 + row * OUT_F + lane * 4) = st;
}

// ------------- combine with fused beta (block-local softmax of wsum) -------------
__global__ void k_combine(const float* __restrict__ zd, const float* __restrict__ zp,
                          const float* __restrict__ wsum, float* __restrict__ out,
                          float* __restrict__ outBeta) {
    __shared__ float sb[6];
    if (threadIdx.x == 0) {
#pragma unroll
        for (int t = 0; t < 2; ++t) {
            float w0 = wsum[t * 3 + 0] / (float)NN;
            float w1 = wsum[t * 3 + 1] / (float)NN;
            float w2 = wsum[t * 3 + 2] / (float)NN;
            float m = fmaxf(w0, fmaxf(w1, w2));
            float e0 = expf(w0 - m), e1 = expf(w1 - m), e2 = expf(w2 - m);
            float inv = 1.f / (e0 + e1 + e2);
            sb[t * 3 + 0] = e0 * inv;
            sb[t * 3 + 1] = e1 * inv;
            sb[t * 3 + 2] = e2 * inv;
        }
    }
    __syncthreads();
    if (blockIdx.x == 0 && threadIdx.x < 6) outBeta[threadIdx.x] = sb[threadIdx.x];
    int i = blockIdx.x * blockDim.x + threadIdx.x;
    if (i >= 2 * NN * OUT_F) return;
    int t = i / (NN * OUT_F);
    int r = i - t * NN * OUT_F;
    int n = r / OUT_F, f = r - n * OUT_F;
    const float* z = (t ? zp : zd) + (size_t)n * (3 * OUT_F) + f;
    out[i] = sb[t * 3 + 0] * z[0] + sb[t * 3 + 1] * z[OUT_F] + sb[t * 3 + 2] * z[2 * OUT_F];
}

// ---------------- host orchestration ----------------
extern "C" void kernel_launch(void* const* d_in, const int* in_sizes, int n_in,
                              void* d_out, int out_size) {
    const float* xd  = (const float*)d_in[0];
    const float* xp  = (const float*)d_in[1];
    const int*   src = (const int*)  d_in[2];
    const int*   dst = (const int*)  d_in[3];
    const float* W1  = (const float*)d_in[4];
    const float* b1  = (const float*)d_in[5];
    const float* W2  = (const float*)d_in[6];
    const float* b2  = (const float*)d_in[7];
    const float* Wpm = (const float*)d_in[8];
    const float* bp  = (const float*)d_in[9];
    const float* q   = (const float*)d_in[10];
    float* out = (float*)d_out;

    float *y, *y2, *zd, *zp, *rout, *rin, *wsum, *csrw;
    int *cnts, *cnt, *base, *cur, *csrs;
    fp16 *x1, *h1, *za1;
    fp16 *wt1a, *wt1b, *wt2a, *wt2b, *wpa, *wpb;
    cudaGetSymbolAddress((void**)&y,    g_y);
    cudaGetSymbolAddress((void**)&y2,   g_y2);
    cudaGetSymbolAddress((void**)&zd,   g_zd);
    cudaGetSymbolAddress((void**)&zp,   g_zp);
    cudaGetSymbolAddress((void**)&rout, g_rout);
    cudaGetSymbolAddress((void**)&rin,  g_rin);
    cudaGetSymbolAddress((void**)&wsum, g_wsum);
    cudaGetSymbolAddress((void**)&cnts, g_cnts);
    cudaGetSymbolAddress((void**)&cnt,  g_cnt);
    cudaGetSymbolAddress((void**)&base, g_base);
    cudaGetSymbolAddress((void**)&cur,  g_cur);
    cudaGetSymbolAddress((void**)&csrs, g_csrs);
    cudaGetSymbolAddress((void**)&csrw, g_csrw);
    cudaGetSymbolAddress((void**)&x1,   g_x1);
    cudaGetSymbolAddress((void**)&h1,   g_h1);
    cudaGetSymbolAddress((void**)&za1,  g_za1);
    cudaGetSymbolAddress((void**)&wt1a, g_wt1a);
    cudaGetSymbolAddress((void**)&wt1b, g_wt1b);
    cudaGetSymbolAddress((void**)&wt2a, g_wt2a);
    cudaGetSymbolAddress((void**)&wt2b, g_wt2b);
    cudaGetSymbolAddress((void**)&wpa,  g_wpa);
    cudaGetSymbolAddress((void**)&wpb,  g_wpb);

    const int T = 256;
    const int mtiles = (NN + 127) / 128;            // 235
    const int gblocks = (NN * 32 + T - 1) / T;      // 3750
    cudaStream_t sd = g_ss.side;

    cudaEventRecord(g_ss.fork, 0);
    cudaStreamWaitEvent(sd, g_ss.fork, 0);
    cudaStreamWaitEvent(g_ss.sc[0], g_ss.fork, 0);

    // kernel #1: half-convert xd (main)
    k_half<<<(NN * IN_F / 4 + T - 1) / T, T>>>(xd, x1, NN * IN_F / 4);
    // kernel #2: half-convert xp (channel stream 0)
    k_half<<<(NN * IN_F / 4 + T - 1) / T, T, 0, g_ss.sc[0]>>>(
        xp, x1 + (size_t)NN * IN_F, NN * IN_F / 4);
    cudaEventRecord(g_ss.xe, g_ss.sc[0]);
    // kernel #3: W1 transform (side)
    k_wts<<<dim3(HID_F / 32, IN_F / 32, 12), dim3(32, 8), 0, sd>>>(W1, wt1a, wt1b, IN_F, HID_F);
    cudaEventRecord(g_ss.w1e, sd);

    // kernel #4: GEMM1 channel 0 (ncu -s 5 -c 1 lands here)
    cudaStreamWaitEvent(0, g_ss.w1e, 0);
    cudaStreamWaitEvent(0, g_ss.xe, 0);
    k_mma<IN_F, HID_F, 0, 0><<<dim3(4 * (HID_F / 128), mtiles), 256>>>(
        x1, wt1a, wt1b, y, NN, 0, 0, nullptr, nullptr, nullptr);
    cudaEventRecord(g_ss.e1[0], 0);

    // side chain: CSR build + remaining weight transforms + wsum zero
    k_zeroi2<<<(12 * NN + T - 1) / T, T, 0, sd>>>(cnts, cnt, 12 * NN);
    k_hist2<<<(12 * EE + T - 1) / T, T, 0, sd>>>(src, dst, cnts, cnt);
    k_prep<<<(12 * NN + T - 1) / T, T, 0, sd>>>(cnts, cnt, rout, rin);
    k_scan<<<12, 1024, 0, sd>>>(cnt, base, cur);
    k_fill<<<(12 * EE + T - 1) / T, T, 0, sd>>>(src, dst, rout, cur, csrs, csrw);
    k_wts<<<dim3(OUT_F / 32, HID_F / 32, 12), dim3(32, 8), 0, sd>>>(W2, wt2a, wt2b, HID_F, OUT_F);
    k_wts1<<<dim3(OUT_F / 32, OUT_F / 32), dim3(32, 8), 0, sd>>>(Wpm, wpa, wpb, OUT_F, OUT_F);
    k_zero<<<1, 32, 0, sd>>>(wsum, 8);
    cudaEventRecord(g_ss.join, sd);

    // GEMM1 channels 1,2 (main)
    for (int c = 1; c < 3; ++c) {
        k_mma<IN_F, HID_F, 0, 0><<<dim3(4 * (HID_F / 128), mtiles), 256>>>(
            x1, wt1a, wt1b, y, NN, c * 4, 0, nullptr, nullptr, nullptr);
        cudaEventRecord(g_ss.e1[c], 0);
    }

    // per-channel pipelines: gag1 -> GEMM2 -> gag2 -> attention GEMM
    for (int c = 0; c < 3; ++c) {
        cudaStream_t s = g_ss.sc[c];
        cudaStreamWaitEvent(s, g_ss.e1[c], 0);
        cudaStreamWaitEvent(s, g_ss.join, 0);
        k_gag1<<<dim3(gblocks, 2), T, 0, s>>>(y, csrs, csrw, base, cnt, rin, b1,
                                              h1, c);
        k_mma<HID_F, OUT_F, 1, 0><<<dim3(4, mtiles), 256, 0, s>>>(
            h1, wt2a, wt2b, y2, NN, c * 4, 0, nullptr, nullptr, nullptr);
        k_gag2<<<dim3(gblocks, 2), T, 0, s>>>(y2, csrs, csrw, base, cnt, rin, b2,
                                              zd, zp, za1, c);
        k_mma<OUT_F, OUT_F, 0, 1><<<dim3(1, (2 * NN + 127) / 128), 256, 0, s>>>(
            za1 + (size_t)c * 2 * NN * OUT_F, wpa, wpb,
            nullptr, 2 * NN, 0, c, bp, q, wsum);
        cudaEventRecord(g_ss.ec[c], s);
    }

    // join all channels, then fused beta+combine on main
    for (int c = 0; c < 3; ++c) cudaStreamWaitEvent(0, g_ss.ec[c], 0);
    k_combine<<<(2 * NN * OUT_F + T - 1) / T, T>>>(zd, zp, wsum, out,
                                                   out + (size_t)2 * NN * OUT_F);
}

// round 15
// speedup vs baseline: 1.7156x; 1.3295x over previous
#include <cuda_runtime.h>
#include <cuda_fp16.h>
#include <cstdint>

#define NN 30000
#define EE 250000
#define IN_F 512
#define HID_F 256
#define OUT_F 128

typedef unsigned long long u64;
typedef __half fp16;

// ---------------- scratch (static device globals; no allocs) ----------------
__device__ float g_y[(size_t)12 * NN * HID_F];
__device__ float g_y2[(size_t)12 * NN * OUT_F];
__device__ float g_zd[(size_t)NN * 3 * OUT_F];
__device__ float g_zp[(size_t)NN * 3 * OUT_F];
__device__ float g_rout[12 * NN];
__device__ float g_rin[12 * NN];
__device__ float g_wsum[8];
__device__ int   g_cnts[12 * NN];
__device__ int   g_cnt[12 * NN];
__device__ int   g_base[12 * NN];
__device__ int   g_cur[12 * NN];
__device__ int   g_csrs[(size_t)12 * EE];
__device__ float g_csrw[(size_t)12 * EE];
__device__ __align__(16) fp16 g_x1[(size_t)2 * NN * IN_F];
__device__ __align__(16) fp16 g_h1[(size_t)6 * NN * HID_F];
__device__ __align__(16) fp16 g_za1[(size_t)2 * NN * 3 * OUT_F];
__device__ __align__(16) fp16 g_wt1a[(size_t)12 * HID_F * IN_F];
__device__ __align__(16) fp16 g_wt2a[(size_t)12 * OUT_F * HID_F];
__device__ __align__(16) fp16 g_wpa[(size_t)OUT_F * OUT_F];
__device__ __align__(16) fp16 g_wpb[(size_t)OUT_F * OUT_F];

__device__ __forceinline__ void fma4(float4& a, float w, const float4 v) {
    a.x += w * v.x; a.y += w * v.y; a.z += w * v.z; a.w += w * v.w;
}
__device__ __forceinline__ int u2cr(int u) {
    int ci = u >> 2;
    int c = (ci == 0) ? 0 : (ci == 1 ? 2 : 3);
    return c * 4 + (u & 3);
}

// ---------------- stream handles (created at static init, pre-checkpoint) ----
struct Streams {
    cudaStream_t side = nullptr;
    cudaStream_t sc[3] = {nullptr, nullptr, nullptr};
    cudaEvent_t fork = nullptr, join = nullptr, w1e = nullptr, xe = nullptr;
    cudaEvent_t e1[3] = {nullptr, nullptr, nullptr};
    cudaEvent_t ec[3] = {nullptr, nullptr, nullptr};
    Streams() {
        cudaStreamCreateWithFlags(&side, cudaStreamNonBlocking);
        cudaEventCreateWithFlags(&fork, cudaEventDisableTiming);
        cudaEventCreateWithFlags(&join, cudaEventDisableTiming);
        cudaEventCreateWithFlags(&w1e, cudaEventDisableTiming);
        cudaEventCreateWithFlags(&xe, cudaEventDisableTiming);
        for (int c = 0; c < 3; ++c) {
            cudaStreamCreateWithFlags(&sc[c], cudaStreamNonBlocking);
            cudaEventCreateWithFlags(&e1[c], cudaEventDisableTiming);
            cudaEventCreateWithFlags(&ec[c], cudaEventDisableTiming);
        }
    }
};
static Streams g_ss;

// ---------------- utility kernels ----------------
__global__ void k_zero(float* __restrict__ p, int n) {
    int i = blockIdx.x * blockDim.x + threadIdx.x;
    if (i < n) p[i] = 0.f;
}
__global__ void k_zeroi2(int* __restrict__ a, int* __restrict__ b, int n) {
    int i = blockIdx.x * blockDim.x + threadIdx.x;
    if (i < n) { a[i] = 0; b[i] = 0; }
}

__global__ void k_hist2(const int* __restrict__ src, const int* __restrict__ dst,
                        int* __restrict__ cnts, int* __restrict__ cntd) {
    int i = blockIdx.x * blockDim.x + threadIdx.x;
    if (i >= 12 * EE) return;
    int u = i / EE, e = i - u * EE;
    int cr = u2cr(u);
    atomicAdd(&cnts[u * NN + src[(size_t)cr * EE + e]], 1);
    atomicAdd(&cntd[u * NN + dst[(size_t)cr * EE + e]], 1);
}

__global__ void k_prep(const int* __restrict__ cnts, const int* __restrict__ cntd,
                       float* __restrict__ rout, float* __restrict__ rin) {
    int i = blockIdx.x * blockDim.x + threadIdx.x;
    if (i >= 12 * NN) return;
    rout[i] = rsqrtf((float)max(cnts[i], 1));
    rin[i]  = rsqrtf((float)max(cntd[i], 1));
}

// deterministic exclusive scan per u (12 blocks, 1024 threads)
__global__ void k_scan(const int* __restrict__ cnt, int* __restrict__ base,
                       int* __restrict__ cur) {
    __shared__ int ws[32];
    __shared__ int carry;
    int u = blockIdx.x;
    const int* c = cnt + u * NN;
    int* b = base + u * NN;
    int* q = cur + u * NN;
    int lane = threadIdx.x & 31, w = threadIdx.x >> 5;
    if (threadIdx.x == 0) carry = 0;
    __syncthreads();
    for (int off = 0; off < NN; off += 1024) {
        int i = off + threadIdx.x;
        int v = (i < NN) ? c[i] : 0;
        int s = v;
#pragma unroll
        for (int o = 1; o < 32; o <<= 1) {
            int t = __shfl_up_sync(0xffffffffu, s, o);
            if (lane >= o) s += t;
        }
        if (lane == 31) ws[w] = s;
        __syncthreads();
        if (w == 0) {
            int t2 = ws[lane];
#pragma unroll
            for (int o = 1; o < 32; o <<= 1) {
                int t = __shfl_up_sync(0xffffffffu, t2, o);
                if (lane >= o) t2 += t;
            }
            ws[lane] = t2;
        }
        __syncthreads();
        int excl = s - v + (w > 0 ? ws[w - 1] : 0) + carry;
        if (i < NN) { b[i] = excl; q[i] = excl; }
        __syncthreads();
        if (threadIdx.x == 1023) carry = excl + v;
        __syncthreads();
    }
}

__global__ void k_fill(const int* __restrict__ src, const int* __restrict__ dst,
                       const float* __restrict__ rout, int* __restrict__ cur,
                       int* __restrict__ csrs, float* __restrict__ csrw) {
    int i = blockIdx.x * blockDim.x + threadIdx.x;
    if (i >= 12 * EE) return;
    int u = i / EE, e = i - u * EE;
    int cr = u2cr(u);
    int s = src[(size_t)cr * EE + e];
    int d = dst[(size_t)cr * EE + e];
    int pos = atomicAdd(&cur[u * NN + d], 1);
    csrs[(size_t)u * EE + pos] = s;
    csrw[(size_t)u * EE + pos] = rout[u * NN + s];
}

// fp32 -> fp16
__global__ void k_half(const float* __restrict__ x, fp16* __restrict__ hi, int n4) {
    int i = blockIdx.x * blockDim.x + threadIdx.x;
    if (i >= n4) return;
    float4 v = ((const float4*)x)[i];
    ((__half2*)hi)[2 * i]     = __floats2half2_rn(v.x, v.y);
    ((__half2*)hi)[2 * i + 1] = __floats2half2_rn(v.z, v.w);
}

// transpose weights (single fp16): W [16][K][N] fp32 (channels 0,2,3) -> [12][N][K]
__global__ void k_wts(const float* __restrict__ W, fp16* __restrict__ t1,
                      int K, int N) {
    __shared__ float tile[32][33];
    int z = blockIdx.z;
    int cz = z >> 2;
    int c = (cz == 0) ? 0 : (cz == 1 ? 2 : 3);
    const float* Wm = W + (size_t)(c * 4 + (z & 3)) * K * N;
    fp16* o1 = t1 + (size_t)z * K * N;
    int k0 = blockIdx.y * 32, n0 = blockIdx.x * 32;
    for (int r = threadIdx.y; r < 32; r += 8)
        tile[r][threadIdx.x] = Wm[(size_t)(k0 + r) * N + n0 + threadIdx.x];
    __syncthreads();
    for (int r = threadIdx.y; r < 32; r += 8)
        o1[(size_t)(n0 + r) * K + k0 + threadIdx.x] =
            __float2half_rn(tile[threadIdx.x][r]);
}

// Wp transpose+split (hi/lo; attention stays 2-chain for exact Wp)
__global__ void k_wts1(const float* __restrict__ W, fp16* __restrict__ t1,
                       fp16* __restrict__ t2, int K, int N) {
    __shared__ float tile[32][33];
    int k0 = blockIdx.y * 32, n0 = blockIdx.x * 32;
    for (int r = threadIdx.y; r < 32; r += 8)
        tile[r][threadIdx.x] = W[(size_t)(k0 + r) * N + n0 + threadIdx.x];
    __syncthreads();
    for (int r = threadIdx.y; r < 32; r += 8) {
        float v = tile[threadIdx.x][r];
        fp16 h = __float2half_rn(v);
        size_t o = (size_t)(n0 + r) * K + k0 + threadIdx.x;
        t1[o] = h;
        t2[o] = __float2half_rn(v - __half2float(h));
    }
}

// ---------------- mma.sync fp16 GEMM, 128x128 tile ----------------
// CHAINS=1: y = A1*B1. CHAINS=2: y = A1*B1 + A1*B2. ATT: fused attention epilogue.
__device__ __forceinline__ void mma16816(float* c, const uint32_t* a, const uint32_t* b) {
    asm volatile("mma.sync.aligned.m16n8k16.row.col.f32.f16.f16.f32 "
                 "{%0,%1,%2,%3}, {%4,%5,%6,%7}, {%8,%9}, {%0,%1,%2,%3};"
                 : "+f"(c[0]), "+f"(c[1]), "+f"(c[2]), "+f"(c[3])
                 : "r"(a[0]), "r"(a[1]), "r"(a[2]), "r"(a[3]), "r"(b[0]), "r"(b[1]));
}

template <int KK, int NOUT, int CH, int CHAINS, int ATT>
__global__ void __launch_bounds__(256, 2) k_mma(
    const fp16* __restrict__ A1b,
    const fp16* __restrict__ Bt1, const fp16* __restrict__ Bt2,
    float* __restrict__ Y, int M, int u0, int attk,
    const float* __restrict__ bp, const float* __restrict__ q,
    float* __restrict__ wsum) {
    __shared__ uint32_t AS[2][2048];
    __shared__ uint32_t BS[2][2048];
    __shared__ float sb[6];

    const int tid = threadIdx.x;
    const int lane = tid & 31;
    const int wid = tid >> 5;
    const int warpM = wid & 3;
    const int warpN = wid >> 2;
    constexpr int NT = NOUT / 128;
    const int u = u0 + blockIdx.x / NT;
    const int bn = (blockIdx.x % NT) * 128;
    const int bm = blockIdx.y * 128;

    if (ATT && tid < 6) sb[tid] = 0.f;

    const int aoff = (CH ? (u >> 2) * 2 : 0) + ((u & 3) >> 1);
    const fp16* A1 = A1b + (size_t)aoff * M * KK;
    const fp16* B1 = Bt1 + (size_t)u * KK * NOUT;
    const fp16* B2 = Bt2 + (size_t)u * KK * NOUT;
    float* Yp = Y + (size_t)u * M * NOUT;

    const fp16* BPass[2] = {B1, B2};

    constexpr int CPP = KK / 32;
    constexpr int NC = CHAINS * CPP;

    float c[2][8][4];
#pragma unroll
    for (int i = 0; i < 2; ++i)
#pragma unroll
        for (int j = 0; j < 8; ++j)
#pragma unroll
            for (int l = 0; l < 4; ++l) c[i][j][l] = 0.f;

    uint4 va[2], vb[2];
    {
#pragma unroll
        for (int i = 0; i < 2; ++i) {
            int u2 = tid + i * 256;
            int m = u2 >> 2, seg = u2 & 3;
            int gm = bm + m;
            va[i] = make_uint4(0, 0, 0, 0);
            if (gm < M)
                va[i] = *(const uint4*)(A1 + (size_t)gm * KK + (seg >> 1) * 16 + (seg & 1) * 8);
            vb[i] = *(const uint4*)(B1 + (size_t)(bn + m) * KK + (seg >> 1) * 16 + (seg & 1) * 8);
        }
    }

#pragma unroll 1
    for (int g = 0; g < NC; ++g) {
        const int buf = g & 1;
#pragma unroll
        for (int i = 0; i < 2; ++i) {
            int u2 = tid + i * 256;
            int m = u2 >> 2, seg = u2 & 3;
            int kb = seg >> 1, h = seg & 1;
            int r = ((m >> 3) & 1) + 2 * h;
            int Lb = (((m & 7) * 4) + seg * 8) & 31;
            int W = ((kb * 8 + (m >> 4)) * 4 + r) * 32 + Lb;
            *(uint4*)&AS[buf][W] = va[i];
            int n = m;
            int Wb = ((kb * 16 + (n >> 3)) * 2 + h) * 32 + Lb;
            *(uint4*)&BS[buf][Wb] = vb[i];
        }
        __syncthreads();

        if (g + 1 < NC) {
            int pass = (g + 1) / CPP, kc = (g + 1) % CPP;
            const fp16* Bg = BPass[pass];
            int koff = kc * 32;
#pragma unroll
            for (int i = 0; i < 2; ++i) {
                int u2 = tid + i * 256;
                int m = u2 >> 2, seg = u2 & 3;
                int gm = bm + m;
                va[i] = make_uint4(0, 0, 0, 0);
                if (gm < M)
                    va[i] = *(const uint4*)(A1 + (size_t)gm * KK + koff +
                                            (seg >> 1) * 16 + (seg & 1) * 8);
                vb[i] = *(const uint4*)(Bg + (size_t)(bn + m) * KK + koff +
                                        (seg >> 1) * 16 + (seg & 1) * 8);
            }
        }

#pragma unroll
        for (int kb = 0; kb < 2; ++kb) {
            uint32_t a[2][4], b[8][2];
#pragma unroll
            for (int mbl = 0; mbl < 2; ++mbl) {
                int mb = warpM * 2 + mbl;
#pragma unroll
                for (int r = 0; r < 4; ++r) {
                    int Lr = (lane + (kb * 2 + (r >> 1)) * 8) & 31;
                    a[mbl][r] = AS[buf][((kb * 8 + mb) * 4 + r) * 32 + Lr];
                }
            }
#pragma unroll
            for (int nbl = 0; nbl < 8; ++nbl) {
                int nb = warpN * 8 + nbl;
#pragma unroll
                for (int h = 0; h < 2; ++h) {
                    int Lr = (lane + (kb * 2 + h) * 8) & 31;
                    b[nbl][h] = BS[buf][((kb * 16 + nb) * 2 + h) * 32 + Lr];
                }
            }
#pragma unroll
            for (int mbl = 0; mbl < 2; ++mbl)
#pragma unroll
                for (int nbl = 0; nbl < 8; ++nbl)
                    mma16816(c[mbl][nbl], a[mbl], b[nbl]);
        }
        __syncthreads();
    }

    if (ATT) {
        float s[2][2] = {{0.f, 0.f}, {0.f, 0.f}};
#pragma unroll
        for (int mbl = 0; mbl < 2; ++mbl)
#pragma unroll
            for (int nbl = 0; nbl < 8; ++nbl) {
                int ncol = warpN * 64 + nbl * 8 + (lane & 3) * 2;
                float bp0 = __ldg(bp + ncol), bp1 = __ldg(bp + ncol + 1);
                float q0 = __ldg(q + ncol), q1 = __ldg(q + ncol + 1);
                s[mbl][0] += tanhf(c[mbl][nbl][0] + bp0) * q0
                           + tanhf(c[mbl][nbl][1] + bp1) * q1;
                s[mbl][1] += tanhf(c[mbl][nbl][2] + bp0) * q0
                           + tanhf(c[mbl][nbl][3] + bp1) * q1;
            }
#pragma unroll
        for (int mbl = 0; mbl < 2; ++mbl)
#pragma unroll
            for (int h2 = 0; h2 < 2; ++h2) {
                float v = s[mbl][h2];
                v += __shfl_xor_sync(0xffffffffu, v, 1);
                v += __shfl_xor_sync(0xffffffffu, v, 2);
                if ((lane & 3) == 0) {
                    int grow = bm + warpM * 32 + mbl * 16 + h2 * 8 + (lane >> 2);
                    if (grow < M) {
                        int t = (grow >= NN) ? 1 : 0;
                        atomicAdd(&sb[t * 3 + attk], v);
                    }
                }
            }
        __syncthreads();
        if (tid < 6 && sb[tid] != 0.f) atomicAdd(&wsum[tid], sb[tid]);
    } else {
#pragma unroll
        for (int mbl = 0; mbl < 2; ++mbl) {
            int mrow = bm + warpM * 32 + mbl * 16 + (lane >> 2);
#pragma unroll
            for (int nbl = 0; nbl < 8; ++nbl) {
                int ncol = bn + warpN * 64 + nbl * 8 + (lane & 3) * 2;
                float* base = Yp + (size_t)mrow * NOUT + ncol;
                if (mrow < M)
                    *(float2*)base = make_float2(c[mbl][nbl][0], c[mbl][nbl][1]);
                if (mrow + 8 < M)
                    *(float2*)(base + (size_t)8 * NOUT) =
                        make_float2(c[mbl][nbl][2], c[mbl][nbl][3]);
            }
        }
    }
}

// --------- fused gather layer1 (one channel; blockIdx.y = type), 2x unroll ---------
__global__ void __launch_bounds__(256) k_gag1(
    const float* __restrict__ y,
    const int* __restrict__ csrs, const float* __restrict__ csrw,
    const int* __restrict__ base, const int* __restrict__ cnt,
    const float* __restrict__ rin, const float* __restrict__ b1,
    fp16* __restrict__ h1, int ci) {
    int gw = (blockIdx.x * blockDim.x + threadIdx.x) >> 5;
    if (gw >= NN) return;
    int lane = threadIdx.x & 31;
    int d = gw;
    int t = blockIdx.y;
    int by = ci * 2 + t;
    int uLo = ci * 4 + t, uHi = uLo + 2;
    int c = (ci == 0) ? 0 : (ci == 1 ? 2 : 3);
    const float* yLo = y + (size_t)uLo * NN * HID_F;
    const float* yHi = y + (size_t)uHi * NN * HID_F;
    const float* bLo = b1 + (c * 4 + t) * HID_F;
    const float* bHi = b1 + (c * 4 + t + 2) * HID_F;

    float4 a0 = make_float4(0, 0, 0, 0), a1 = a0, e0 = a0, e1 = a0;
    float4 c0 = a0, c1 = a0, f0 = a0, f1 = a0;
    {
        int b = base[uLo * NN + d], n = cnt[uLo * NN + d];
        const int* cs = csrs + (size_t)uLo * EE;
        const float* cw = csrw + (size_t)uLo * EE;
        int i = 0;
        for (; i + 2 <= n; i += 2) {
            int s0 = cs[b + i], s1 = cs[b + i + 1];
            float w0 = cw[b + i], w1 = cw[b + i + 1];
            const float4* r0 = (const float4*)(yLo + (size_t)s0 * HID_F);
            const float4* r1 = (const float4*)(yLo + (size_t)s1 * HID_F);
            fma4(a0, w0, r0[lane]);
            fma4(a1, w0, r0[32 + lane]);
            fma4(e0, w1, r1[lane]);
            fma4(e1, w1, r1[32 + lane]);
        }
        if (i < n) {
            int s0 = cs[b + i];
            float w0 = cw[b + i];
            const float4* r0 = (const float4*)(yLo + (size_t)s0 * HID_F);
            fma4(a0, w0, r0[lane]);
            fma4(a1, w0, r0[32 + lane]);
        }
    }
    {
        int b = base[uHi * NN + d], n = cnt[uHi * NN + d];
        const int* cs = csrs + (size_t)uHi * EE;
        const float* cw = csrw + (size_t)uHi * EE;
        int i = 0;
        for (; i + 2 <= n; i += 2) {
            int s0 = cs[b + i], s1 = cs[b + i + 1];
            float w0 = cw[b + i], w1 = cw[b + i + 1];
            const float4* r0 = (const float4*)(yHi + (size_t)s0 * HID_F);
            const float4* r1 = (const float4*)(yHi + (size_t)s1 * HID_F);
            fma4(c0, w0, r0[lane]);
            fma4(c1, w0, r0[32 + lane]);
            fma4(f0, w1, r1[lane]);
            fma4(f1, w1, r1[32 + lane]);
        }
        if (i < n) {
            int s0 = cs[b + i];
            float w0 = cw[b + i];
            const float4* r0 = (const float4*)(yHi + (size_t)s0 * HID_F);
            fma4(c0, w0, r0[lane]);
            fma4(c1, w0, r0[32 + lane]);
        }
    }
    a0.x += e0.x; a0.y += e0.y; a0.z += e0.z; a0.w += e0.w;
    a1.x += e1.x; a1.y += e1.y; a1.z += e1.z; a1.w += e1.w;
    c0.x += f0.x; c0.y += f0.y; c0.z += f0.z; c0.w += f0.w;
    c1.x += f1.x; c1.y += f1.y; c1.z += f1.z; c1.w += f1.w;

    float rl = rin[uLo * NN + d], rh = rin[uHi * NN + d];
    fp16* o1 = h1 + (size_t)by * NN * HID_F;
#pragma unroll
    for (int ch = 0; ch < 2; ++ch) {
        float4 A = ch ? a1 : a0, C = ch ? c1 : c0;
        float4 x = ((const float4*)bLo)[ch * 32 + lane];
        float4 yb = ((const float4*)bHi)[ch * 32 + lane];
        float r0 = fmaxf(x.x + yb.x + rl * A.x + rh * C.x, 0.f);
        float r1 = fmaxf(x.y + yb.y + rl * A.y + rh * C.y, 0.f);
        float r2 = fmaxf(x.z + yb.z + rl * A.z + rh * C.z, 0.f);
        float r3 = fmaxf(x.w + yb.w + rl * A.w + rh * C.w, 0.f);
        __half2 p0 = __floats2half2_rn(r0, r1);
        __half2 p1 = __floats2half2_rn(r2, r3);
        uint2 st;
        st.x = *(unsigned*)&p0; st.y = *(unsigned*)&p1;
        size_t off = (size_t)d * HID_F + ch * 128 + lane * 4;
        *(uint2*)(o1 + off) = st;
    }
}

// --------- fused gather layer2 + z fp16 (channel-contiguous za rows) ---------
__global__ void __launch_bounds__(256) k_gag2(
    const float* __restrict__ y2,
    const int* __restrict__ csrs, const float* __restrict__ csrw,
    const int* __restrict__ base, const int* __restrict__ cnt,
    const float* __restrict__ rin, const float* __restrict__ b2,
    float* __restrict__ zd, float* __restrict__ zp,
    fp16* __restrict__ za1, int ci) {
    int gw = (blockIdx.x * blockDim.x + threadIdx.x) >> 5;
    if (gw >= NN) return;
    int lane = threadIdx.x & 31;
    int d = gw;
    int t = blockIdx.y;
    int uLo = ci * 4 + t, uHi = uLo + 2;
    int c = (ci == 0) ? 0 : (ci == 1 ? 2 : 3);
    const float* yLo = y2 + (size_t)uLo * NN * OUT_F;
    const float* yHi = y2 + (size_t)uHi * NN * OUT_F;
    const float* bLo = b2 + (c * 4 + t) * OUT_F;
    const float* bHi = b2 + (c * 4 + t + 2) * OUT_F;

    float4 a0 = make_float4(0, 0, 0, 0), e0 = a0, c0 = a0, f0 = a0;
    {
        int b = base[uLo * NN + d], n = cnt[uLo * NN + d];
        const int* cs = csrs + (size_t)uLo * EE;
        const float* cw = csrw + (size_t)uLo * EE;
        int i = 0;
        for (; i + 2 <= n; i += 2) {
            fma4(a0, cw[b + i], ((const float4*)(yLo + (size_t)cs[b + i] * OUT_F))[lane]);
            fma4(e0, cw[b + i + 1],
                 ((const float4*)(yLo + (size_t)cs[b + i + 1] * OUT_F))[lane]);
        }
        if (i < n)
            fma4(a0, cw[b + i], ((const float4*)(yLo + (size_t)cs[b + i] * OUT_F))[lane]);
    }
    {
        int b = base[uHi * NN + d], n = cnt[uHi * NN + d];
        const int* cs = csrs + (size_t)uHi * EE;
        const float* cw = csrw + (size_t)uHi * EE;
        int i = 0;
        for (; i + 2 <= n; i += 2) {
            fma4(c0, cw[b + i], ((const float4*)(yHi + (size_t)cs[b + i] * OUT_F))[lane]);
            fma4(f0, cw[b + i + 1],
                 ((const float4*)(yHi + (size_t)cs[b + i + 1] * OUT_F))[lane]);
        }
        if (i < n)
            fma4(c0, cw[b + i], ((const float4*)(yHi + (size_t)cs[b + i] * OUT_F))[lane]);
    }
    a0.x += e0.x; a0.y += e0.y; a0.z += e0.z; a0.w += e0.w;
    c0.x += f0.x; c0.y += f0.y; c0.z += f0.z; c0.w += f0.w;

    float rl = rin[uLo * NN + d], rh = rin[uHi * NN + d];
    float4 x = ((const float4*)bLo)[lane], yb = ((const float4*)bHi)[lane];
    float4 res;
    res.x = fmaxf(x.x + yb.x + rl * a0.x + rh * c0.x, 0.f);
    res.y = fmaxf(x.y + yb.y + rl * a0.y + rh * c0.y, 0.f);
    res.z = fmaxf(x.z + yb.z + rl * a0.z + rh * c0.z, 0.f);
    res.w = fmaxf(x.w + yb.w + rl * a0.w + rh * c0.w, 0.f);
    float* zt = t ? zp : zd;
    *(float4*)(zt + (size_t)d * (3 * OUT_F) + ci * OUT_F + lane * 4) = res;

    size_t row = (size_t)ci * 2 * NN + (size_t)t * NN + d;
    __half2 p0 = __floats2half2_rn(res.x, res.y);
    __half2 p1 = __floats2half2_rn(res.z, res.w);
    uint2 st;
    st.x = *(unsigned*)&p0; st.y = *(unsigned*)&p1;
    *(uint2*)(za1 + row * OUT_F + lane * 4) = st;
}

// ------------- combine with fused beta (block-local softmax of wsum) -------------
__global__ void k_combine(const float* __restrict__ zd, const float* __restrict__ zp,
                          const float* __restrict__ wsum, float* __restrict__ out,
                          float* __restrict__ outBeta) {
    __shared__ float sb[6];
    if (threadIdx.x == 0) {
#pragma unroll
        for (int t = 0; t < 2; ++t) {
            float w0 = wsum[t * 3 + 0] / (float)NN;
            float w1 = wsum[t * 3 + 1] / (float)NN;
            float w2 = wsum[t * 3 + 2] / (float)NN;
            float m = fmaxf(w0, fmaxf(w1, w2));
            float e0 = expf(w0 - m), e1 = expf(w1 - m), e2 = expf(w2 - m);
            float inv = 1.f / (e0 + e1 + e2);
            sb[t * 3 + 0] = e0 * inv;
            sb[t * 3 + 1] = e1 * inv;
            sb[t * 3 + 2] = e2 * inv;
        }
    }
    __syncthreads();
    if (blockIdx.x == 0 && threadIdx.x < 6) outBeta[threadIdx.x] = sb[threadIdx.x];
    int i = blockIdx.x * blockDim.x + threadIdx.x;
    if (i >= 2 * NN * OUT_F) return;
    int t = i / (NN * OUT_F);
    int r = i - t * NN * OUT_F;
    int n = r / OUT_F, f = r - n * OUT_F;
    const float* z = (t ? zp : zd) + (size_t)n * (3 * OUT_F) + f;
    out[i] = sb[t * 3 + 0] * z[0] + sb[t * 3 + 1] * z[OUT_F] + sb[t * 3 + 2] * z[2 * OUT_F];
}

// ---------------- host orchestration ----------------
extern "C" void kernel_launch(void* const* d_in, const int* in_sizes, int n_in,
                              void* d_out, int out_size) {
    const float* xd  = (const float*)d_in[0];
    const float* xp  = (const float*)d_in[1];
    const int*   src = (const int*)  d_in[2];
    const int*   dst = (const int*)  d_in[3];
    const float* W1  = (const float*)d_in[4];
    const float* b1  = (const float*)d_in[5];
    const float* W2  = (const float*)d_in[6];
    const float* b2  = (const float*)d_in[7];
    const float* Wpm = (const float*)d_in[8];
    const float* bp  = (const float*)d_in[9];
    const float* q   = (const float*)d_in[10];
    float* out = (float*)d_out;

    float *y, *y2, *zd, *zp, *rout, *rin, *wsum, *csrw;
    int *cnts, *cnt, *base, *cur, *csrs;
    fp16 *x1, *h1, *za1;
    fp16 *wt1a, *wt2a, *wpa, *wpb;
    cudaGetSymbolAddress((void**)&y,    g_y);
    cudaGetSymbolAddress((void**)&y2,   g_y2);
    cudaGetSymbolAddress((void**)&zd,   g_zd);
    cudaGetSymbolAddress((void**)&zp,   g_zp);
    cudaGetSymbolAddress((void**)&rout, g_rout);
    cudaGetSymbolAddress((void**)&rin,  g_rin);
    cudaGetSymbolAddress((void**)&wsum, g_wsum);
    cudaGetSymbolAddress((void**)&cnts, g_cnts);
    cudaGetSymbolAddress((void**)&cnt,  g_cnt);
    cudaGetSymbolAddress((void**)&base, g_base);
    cudaGetSymbolAddress((void**)&cur,  g_cur);
    cudaGetSymbolAddress((void**)&csrs, g_csrs);
    cudaGetSymbolAddress((void**)&csrw, g_csrw);
    cudaGetSymbolAddress((void**)&x1,   g_x1);
    cudaGetSymbolAddress((void**)&h1,   g_h1);
    cudaGetSymbolAddress((void**)&za1,  g_za1);
    cudaGetSymbolAddress((void**)&wt1a, g_wt1a);
    cudaGetSymbolAddress((void**)&wt2a, g_wt2a);
    cudaGetSymbolAddress((void**)&wpa,  g_wpa);
    cudaGetSymbolAddress((void**)&wpb,  g_wpb);

    const int T = 256;
    const int mtiles = (NN + 127) / 128;            // 235
    const int gblocks = (NN * 32 + T - 1) / T;      // 3750
    cudaStream_t sd = g_ss.side;

    cudaEventRecord(g_ss.fork, 0);
    cudaStreamWaitEvent(sd, g_ss.fork, 0);
    cudaStreamWaitEvent(g_ss.sc[0], g_ss.fork, 0);

    // kernel #1: half-convert xd (main)
    k_half<<<(NN * IN_F / 4 + T - 1) / T, T>>>(xd, x1, NN * IN_F / 4);
    // kernel #2: half-convert xp (channel stream 0)
    k_half<<<(NN * IN_F / 4 + T - 1) / T, T, 0, g_ss.sc[0]>>>(
        xp, x1 + (size_t)NN * IN_F, NN * IN_F / 4);
    cudaEventRecord(g_ss.xe, g_ss.sc[0]);
    // kernel #3: W1 transform (side)
    k_wts<<<dim3(HID_F / 32, IN_F / 32, 12), dim3(32, 8), 0, sd>>>(W1, wt1a, IN_F, HID_F);
    cudaEventRecord(g_ss.w1e, sd);

    // kernel #4: GEMM1 channel 0 (ncu -s 5 -c 1 lands here)
    cudaStreamWaitEvent(0, g_ss.w1e, 0);
    cudaStreamWaitEvent(0, g_ss.xe, 0);
    k_mma<IN_F, HID_F, 0, 1, 0><<<dim3(4 * (HID_F / 128), mtiles), 256>>>(
        x1, wt1a, wt1a, y, NN, 0, 0, nullptr, nullptr, nullptr);
    cudaEventRecord(g_ss.e1[0], 0);

    // side chain: CSR build + remaining weight transforms + wsum zero
    k_zeroi2<<<(12 * NN + T - 1) / T, T, 0, sd>>>(cnts, cnt, 12 * NN);
    k_hist2<<<(12 * EE + T - 1) / T, T, 0, sd>>>(src, dst, cnts, cnt);
    k_prep<<<(12 * NN + T - 1) / T, T, 0, sd>>>(cnts, cnt, rout, rin);
    k_scan<<<12, 1024, 0, sd>>>(cnt, base, cur);
    k_fill<<<(12 * EE + T - 1) / T, T, 0, sd>>>(src, dst, rout, cur, csrs, csrw);
    k_wts<<<dim3(OUT_F / 32, HID_F / 32, 12), dim3(32, 8), 0, sd>>>(W2, wt2a, HID_F, OUT_F);
    k_wts1<<<dim3(OUT_F / 32, OUT_F / 32), dim3(32, 8), 0, sd>>>(Wpm, wpa, wpb, OUT_F, OUT_F);
    k_zero<<<1, 32, 0, sd>>>(wsum, 8);
    cudaEventRecord(g_ss.join, sd);

    // GEMM1 channels 1,2 (main)
    for (int c = 1; c < 3; ++c) {
        k_mma<IN_F, HID_F, 0, 1, 0><<<dim3(4 * (HID_F / 128), mtiles), 256>>>(
            x1, wt1a, wt1a, y, NN, c * 4, 0, nullptr, nullptr, nullptr);
        cudaEventRecord(g_ss.e1[c], 0);
    }

    // per-channel pipelines: gag1 -> GEMM2 -> gag2 -> attention GEMM
    for (int c = 0; c < 3; ++c) {
        cudaStream_t s = g_ss.sc[c];
        cudaStreamWaitEvent(s, g_ss.e1[c], 0);
        cudaStreamWaitEvent(s, g_ss.join, 0);
        k_gag1<<<dim3(gblocks, 2), T, 0, s>>>(y, csrs, csrw, base, cnt, rin, b1,
                                              h1, c);
        k_mma<HID_F, OUT_F, 1, 1, 0><<<dim3(4, mtiles), 256, 0, s>>>(
            h1, wt2a, wt2a, y2, NN, c * 4, 0, nullptr, nullptr, nullptr);
        k_gag2<<<dim3(gblocks, 2), T, 0, s>>>(y2, csrs, csrw, base, cnt, rin, b2,
                                              zd, zp, za1, c);
        k_mma<OUT_F, OUT_F, 0, 2, 1><<<dim3(1, (2 * NN + 127) / 128), 256, 0, s>>>(
            za1 + (size_t)c * 2 * NN * OUT_F, wpa, wpb,
            nullptr, 2 * NN, 0, c, bp, q, wsum);
        cudaEventRecord(g_ss.ec[c], s);
    }

    // join all channels, then fused beta+combine on main
    for (int c = 0; c < 3; ++c) cudaStreamWaitEvent(0, g_ss.ec[c], 0);
    k_combine<<<(2 * NN * OUT_F + T - 1) / T, T>>>(zd, zp, wsum, out,
                                                   out + (size_t)2 * NN * OUT_F);
}

// round 16
// speedup vs baseline: 1.8769x; 1.0940x over previous
#include <cuda_runtime.h>
#include <cuda_fp16.h>
#include <cstdint>

#define NN 30000
#define EE 250000
#define IN_F 512
#define HID_F 256
#define OUT_F 128

typedef unsigned long long u64;
typedef __half fp16;

// ---------------- scratch (static device globals; no allocs) ----------------
__device__ __align__(16) fp16 g_y[(size_t)12 * NN * HID_F];    // layer-1 outputs (fp16)
__device__ __align__(16) fp16 g_y2[(size_t)12 * NN * OUT_F];   // layer-2 outputs (fp16)
__device__ float g_zd[(size_t)NN * 3 * OUT_F];
__device__ float g_zp[(size_t)NN * 3 * OUT_F];
__device__ float g_rout[12 * NN];
__device__ float g_rin[12 * NN];
__device__ float g_wsum[8];
__device__ int   g_cnts[12 * NN];
__device__ int   g_cnt[12 * NN];
__device__ int   g_base[12 * NN];
__device__ int   g_cur[12 * NN];
__device__ int   g_csrs[(size_t)12 * EE];
__device__ float g_csrw[(size_t)12 * EE];
__device__ __align__(16) fp16 g_x1[(size_t)2 * NN * IN_F];
__device__ __align__(16) fp16 g_h1[(size_t)6 * NN * HID_F];
__device__ __align__(16) fp16 g_za1[(size_t)2 * NN * 3 * OUT_F];
__device__ __align__(16) fp16 g_wt1a[(size_t)12 * HID_F * IN_F];
__device__ __align__(16) fp16 g_wt2a[(size_t)12 * OUT_F * HID_F];
__device__ __align__(16) fp16 g_wpa[(size_t)OUT_F * OUT_F];
__device__ __align__(16) fp16 g_wpb[(size_t)OUT_F * OUT_F];

__device__ __forceinline__ void fma4h(float4& a, float w, uint2 v) {
    float2 p = __half22float2(*(__half2*)&v.x);
    float2 q = __half22float2(*(__half2*)&v.y);
    a.x += w * p.x; a.y += w * p.y; a.z += w * q.x; a.w += w * q.y;
}
__device__ __forceinline__ int u2cr(int u) {
    int ci = u >> 2;
    int c = (ci == 0) ? 0 : (ci == 1 ? 2 : 3);
    return c * 4 + (u & 3);
}

// ---------------- stream handles (created at static init, pre-checkpoint) ----
struct Streams {
    cudaStream_t side = nullptr;
    cudaStream_t sc[3] = {nullptr, nullptr, nullptr};
    cudaEvent_t fork = nullptr, join = nullptr, w1e = nullptr, xe = nullptr;
    cudaEvent_t e1[3] = {nullptr, nullptr, nullptr};
    cudaEvent_t ec[3] = {nullptr, nullptr, nullptr};
    Streams() {
        cudaStreamCreateWithFlags(&side, cudaStreamNonBlocking);
        cudaEventCreateWithFlags(&fork, cudaEventDisableTiming);
        cudaEventCreateWithFlags(&join, cudaEventDisableTiming);
        cudaEventCreateWithFlags(&w1e, cudaEventDisableTiming);
        cudaEventCreateWithFlags(&xe, cudaEventDisableTiming);
        for (int c = 0; c < 3; ++c) {
            cudaStreamCreateWithFlags(&sc[c], cudaStreamNonBlocking);
            cudaEventCreateWithFlags(&e1[c], cudaEventDisableTiming);
            cudaEventCreateWithFlags(&ec[c], cudaEventDisableTiming);
        }
    }
};
static Streams g_ss;

// ---------------- utility kernels ----------------
__global__ void k_zero(float* __restrict__ p, int n) {
    int i = blockIdx.x * blockDim.x + threadIdx.x;
    if (i < n) p[i] = 0.f;
}
__global__ void k_zeroi2(int* __restrict__ a, int* __restrict__ b, int n) {
    int i = blockIdx.x * blockDim.x + threadIdx.x;
    if (i < n) { a[i] = 0; b[i] = 0; }
}

__global__ void k_hist2(const int* __restrict__ src, const int* __restrict__ dst,
                        int* __restrict__ cnts, int* __restrict__ cntd) {
    int i = blockIdx.x * blockDim.x + threadIdx.x;
    if (i >= 12 * EE) return;
    int u = i / EE, e = i - u * EE;
    int cr = u2cr(u);
    atomicAdd(&cnts[u * NN + src[(size_t)cr * EE + e]], 1);
    atomicAdd(&cntd[u * NN + dst[(size_t)cr * EE + e]], 1);
}

__global__ void k_prep(const int* __restrict__ cnts, const int* __restrict__ cntd,
                       float* __restrict__ rout, float* __restrict__ rin) {
    int i = blockIdx.x * blockDim.x + threadIdx.x;
    if (i >= 12 * NN) return;
    rout[i] = rsqrtf((float)max(cnts[i], 1));
    rin[i]  = rsqrtf((float)max(cntd[i], 1));
}

// deterministic exclusive scan per u (12 blocks, 1024 threads)
__global__ void k_scan(const int* __restrict__ cnt, int* __restrict__ base,
                       int* __restrict__ cur) {
    __shared__ int ws[32];
    __shared__ int carry;
    int u = blockIdx.x;
    const int* c = cnt + u * NN;
    int* b = base + u * NN;
    int* q = cur + u * NN;
    int lane = threadIdx.x & 31, w = threadIdx.x >> 5;
    if (threadIdx.x == 0) carry = 0;
    __syncthreads();
    for (int off = 0; off < NN; off += 1024) {
        int i = off + threadIdx.x;
        int v = (i < NN) ? c[i] : 0;
        int s = v;
#pragma unroll
        for (int o = 1; o < 32; o <<= 1) {
            int t = __shfl_up_sync(0xffffffffu, s, o);
            if (lane >= o) s += t;
        }
        if (lane == 31) ws[w] = s;
        __syncthreads();
        if (w == 0) {
            int t2 = ws[lane];
#pragma unroll
            for (int o = 1; o < 32; o <<= 1) {
                int t = __shfl_up_sync(0xffffffffu, t2, o);
                if (lane >= o) t2 += t;
            }
            ws[lane] = t2;
        }
        __syncthreads();
        int excl = s - v + (w > 0 ? ws[w - 1] : 0) + carry;
        if (i < NN) { b[i] = excl; q[i] = excl; }
        __syncthreads();
        if (threadIdx.x == 1023) carry = excl + v;
        __syncthreads();
    }
}

__global__ void k_fill(const int* __restrict__ src, const int* __restrict__ dst,
                       const float* __restrict__ rout, int* __restrict__ cur,
                       int* __restrict__ csrs, float* __restrict__ csrw) {
    int i = blockIdx.x * blockDim.x + threadIdx.x;
    if (i >= 12 * EE) return;
    int u = i / EE, e = i - u * EE;
    int cr = u2cr(u);
    int s = src[(size_t)cr * EE + e];
    int d = dst[(size_t)cr * EE + e];
    int pos = atomicAdd(&cur[u * NN + d], 1);
    csrs[(size_t)u * EE + pos] = s;
    csrw[(size_t)u * EE + pos] = rout[u * NN + s];
}

// fp32 -> fp16
__global__ void k_half(const float* __restrict__ x, fp16* __restrict__ hi, int n4) {
    int i = blockIdx.x * blockDim.x + threadIdx.x;
    if (i >= n4) return;
    float4 v = ((const float4*)x)[i];
    ((__half2*)hi)[2 * i]     = __floats2half2_rn(v.x, v.y);
    ((__half2*)hi)[2 * i + 1] = __floats2half2_rn(v.z, v.w);
}

// transpose weights (single fp16)
__global__ void k_wts(const float* __restrict__ W, fp16* __restrict__ t1,
                      int K, int N) {
    __shared__ float tile[32][33];
    int z = blockIdx.z;
    int cz = z >> 2;
    int c = (cz == 0) ? 0 : (cz == 1 ? 2 : 3);
    const float* Wm = W + (size_t)(c * 4 + (z & 3)) * K * N;
    fp16* o1 = t1 + (size_t)z * K * N;
    int k0 = blockIdx.y * 32, n0 = blockIdx.x * 32;
    for (int r = threadIdx.y; r < 32; r += 8)
        tile[r][threadIdx.x] = Wm[(size_t)(k0 + r) * N + n0 + threadIdx.x];
    __syncthreads();
    for (int r = threadIdx.y; r < 32; r += 8)
        o1[(size_t)(n0 + r) * K + k0 + threadIdx.x] =
            __float2half_rn(tile[threadIdx.x][r]);
}

// Wp transpose+split (hi/lo; attention stays 2-chain for exact Wp)
__global__ void k_wts1(const float* __restrict__ W, fp16* __restrict__ t1,
                       fp16* __restrict__ t2, int K, int N) {
    __shared__ float tile[32][33];
    int k0 = blockIdx.y * 32, n0 = blockIdx.x * 32;
    for (int r = threadIdx.y; r < 32; r += 8)
        tile[r][threadIdx.x] = W[(size_t)(k0 + r) * N + n0 + threadIdx.x];
    __syncthreads();
    for (int r = threadIdx.y; r < 32; r += 8) {
        float v = tile[threadIdx.x][r];
        fp16 h = __float2half_rn(v);
        size_t o = (size_t)(n0 + r) * K + k0 + threadIdx.x;
        t1[o] = h;
        t2[o] = __float2half_rn(v - __half2float(h));
    }
}

// ---------------- mma.sync fp16 GEMM, 128x128 tile; fp16 epilogue ----------------
__device__ __forceinline__ void mma16816(float* c, const uint32_t* a, const uint32_t* b) {
    asm volatile("mma.sync.aligned.m16n8k16.row.col.f32.f16.f16.f32 "
                 "{%0,%1,%2,%3}, {%4,%5,%6,%7}, {%8,%9}, {%0,%1,%2,%3};"
                 : "+f"(c[0]), "+f"(c[1]), "+f"(c[2]), "+f"(c[3])
                 : "r"(a[0]), "r"(a[1]), "r"(a[2]), "r"(a[3]), "r"(b[0]), "r"(b[1]));
}

template <int KK, int NOUT, int CH, int CHAINS, int ATT>
__global__ void __launch_bounds__(256, 2) k_mma(
    const fp16* __restrict__ A1b,
    const fp16* __restrict__ Bt1, const fp16* __restrict__ Bt2,
    fp16* __restrict__ Y, int M, int u0, int attk,
    const float* __restrict__ bp, const float* __restrict__ q,
    float* __restrict__ wsum) {
    __shared__ uint32_t AS[2][2048];
    __shared__ uint32_t BS[2][2048];
    __shared__ float sb[6];

    const int tid = threadIdx.x;
    const int lane = tid & 31;
    const int wid = tid >> 5;
    const int warpM = wid & 3;
    const int warpN = wid >> 2;
    constexpr int NT = NOUT / 128;
    const int u = u0 + blockIdx.x / NT;
    const int bn = (blockIdx.x % NT) * 128;
    const int bm = blockIdx.y * 128;

    if (ATT && tid < 6) sb[tid] = 0.f;

    const int aoff = (CH ? (u >> 2) * 2 : 0) + ((u & 3) >> 1);
    const fp16* A1 = A1b + (size_t)aoff * M * KK;
    const fp16* B1 = Bt1 + (size_t)u * KK * NOUT;
    const fp16* B2 = Bt2 + (size_t)u * KK * NOUT;
    fp16* Yp = Y + (size_t)u * M * NOUT;

    const fp16* BPass[2] = {B1, B2};

    constexpr int CPP = KK / 32;
    constexpr int NC = CHAINS * CPP;

    float c[2][8][4];
#pragma unroll
    for (int i = 0; i < 2; ++i)
#pragma unroll
        for (int j = 0; j < 8; ++j)
#pragma unroll
            for (int l = 0; l < 4; ++l) c[i][j][l] = 0.f;

    uint4 va[2], vb[2];
    {
#pragma unroll
        for (int i = 0; i < 2; ++i) {
            int u2 = tid + i * 256;
            int m = u2 >> 2, seg = u2 & 3;
            int gm = bm + m;
            va[i] = make_uint4(0, 0, 0, 0);
            if (gm < M)
                va[i] = *(const uint4*)(A1 + (size_t)gm * KK + (seg >> 1) * 16 + (seg & 1) * 8);
            vb[i] = *(const uint4*)(B1 + (size_t)(bn + m) * KK + (seg >> 1) * 16 + (seg & 1) * 8);
        }
    }

#pragma unroll 1
    for (int g = 0; g < NC; ++g) {
        const int buf = g & 1;
#pragma unroll
        for (int i = 0; i < 2; ++i) {
            int u2 = tid + i * 256;
            int m = u2 >> 2, seg = u2 & 3;
            int kb = seg >> 1, h = seg & 1;
            int r = ((m >> 3) & 1) + 2 * h;
            int Lb = (((m & 7) * 4) + seg * 8) & 31;
            int W = ((kb * 8 + (m >> 4)) * 4 + r) * 32 + Lb;
            *(uint4*)&AS[buf][W] = va[i];
            int n = m;
            int Wb = ((kb * 16 + (n >> 3)) * 2 + h) * 32 + Lb;
            *(uint4*)&BS[buf][Wb] = vb[i];
        }
        __syncthreads();

        if (g + 1 < NC) {
            int pass = (g + 1) / CPP, kc = (g + 1) % CPP;
            const fp16* Bg = BPass[pass];
            int koff = kc * 32;
#pragma unroll
            for (int i = 0; i < 2; ++i) {
                int u2 = tid + i * 256;
                int m = u2 >> 2, seg = u2 & 3;
                int gm = bm + m;
                va[i] = make_uint4(0, 0, 0, 0);
                if (gm < M)
                    va[i] = *(const uint4*)(A1 + (size_t)gm * KK + koff +
                                            (seg >> 1) * 16 + (seg & 1) * 8);
                vb[i] = *(const uint4*)(Bg + (size_t)(bn + m) * KK + koff +
                                        (seg >> 1) * 16 + (seg & 1) * 8);
            }
        }

#pragma unroll
        for (int kb = 0; kb < 2; ++kb) {
            uint32_t a[2][4], b[8][2];
#pragma unroll
            for (int mbl = 0; mbl < 2; ++mbl) {
                int mb = warpM * 2 + mbl;
#pragma unroll
                for (int r = 0; r < 4; ++r) {
                    int Lr = (lane + (kb * 2 + (r >> 1)) * 8) & 31;
                    a[mbl][r] = AS[buf][((kb * 8 + mb) * 4 + r) * 32 + Lr];
                }
            }
#pragma unroll
            for (int nbl = 0; nbl < 8; ++nbl) {
                int nb = warpN * 8 + nbl;
#pragma unroll
                for (int h = 0; h < 2; ++h) {
                    int Lr = (lane + (kb * 2 + h) * 8) & 31;
                    b[nbl][h] = BS[buf][((kb * 16 + nb) * 2 + h) * 32 + Lr];
                }
            }
#pragma unroll
            for (int mbl = 0; mbl < 2; ++mbl)
#pragma unroll
                for (int nbl = 0; nbl < 8; ++nbl)
                    mma16816(c[mbl][nbl], a[mbl], b[nbl]);
        }
        __syncthreads();
    }

    if (ATT) {
        float s[2][2] = {{0.f, 0.f}, {0.f, 0.f}};
#pragma unroll
        for (int mbl = 0; mbl < 2; ++mbl)
#pragma unroll
            for (int nbl = 0; nbl < 8; ++nbl) {
                int ncol = warpN * 64 + nbl * 8 + (lane & 3) * 2;
                float bp0 = __ldg(bp + ncol), bp1 = __ldg(bp + ncol + 1);
                float q0 = __ldg(q + ncol), q1 = __ldg(q + ncol + 1);
                s[mbl][0] += tanhf(c[mbl][nbl][0] + bp0) * q0
                           + tanhf(c[mbl][nbl][1] + bp1) * q1;
                s[mbl][1] += tanhf(c[mbl][nbl][2] + bp0) * q0
                           + tanhf(c[mbl][nbl][3] + bp1) * q1;
            }
#pragma unroll
        for (int mbl = 0; mbl < 2; ++mbl)
#pragma unroll
            for (int h2 = 0; h2 < 2; ++h2) {
                float v = s[mbl][h2];
                v += __shfl_xor_sync(0xffffffffu, v, 1);
                v += __shfl_xor_sync(0xffffffffu, v, 2);
                if ((lane & 3) == 0) {
                    int grow = bm + warpM * 32 + mbl * 16 + h2 * 8 + (lane >> 2);
                    if (grow < M) {
                        int t = (grow >= NN) ? 1 : 0;
                        atomicAdd(&sb[t * 3 + attk], v);
                    }
                }
            }
        __syncthreads();
        if (tid < 6 && sb[tid] != 0.f) atomicAdd(&wsum[tid], sb[tid]);
    } else {
#pragma unroll
        for (int mbl = 0; mbl < 2; ++mbl) {
            int mrow = bm + warpM * 32 + mbl * 16 + (lane >> 2);
#pragma unroll
            for (int nbl = 0; nbl < 8; ++nbl) {
                int ncol = bn + warpN * 64 + nbl * 8 + (lane & 3) * 2;
                fp16* bptr = Yp + (size_t)mrow * NOUT + ncol;
                if (mrow < M)
                    *(__half2*)bptr = __floats2half2_rn(c[mbl][nbl][0], c[mbl][nbl][1]);
                if (mrow + 8 < M)
                    *(__half2*)(bptr + (size_t)8 * NOUT) =
                        __floats2half2_rn(c[mbl][nbl][2], c[mbl][nbl][3]);
            }
        }
    }
}

// --------- fused gather layer1 (fp16 y rows), 2x unroll ---------
__global__ void __launch_bounds__(256) k_gag1(
    const fp16* __restrict__ y,
    const int* __restrict__ csrs, const float* __restrict__ csrw,
    const int* __restrict__ base, const int* __restrict__ cnt,
    const float* __restrict__ rin, const float* __restrict__ b1,
    fp16* __restrict__ h1, int ci) {
    int gw = (blockIdx.x * blockDim.x + threadIdx.x) >> 5;
    if (gw >= NN) return;
    int lane = threadIdx.x & 31;
    int d = gw;
    int t = blockIdx.y;
    int by = ci * 2 + t;
    int uLo = ci * 4 + t, uHi = uLo + 2;
    int c = (ci == 0) ? 0 : (ci == 1 ? 2 : 3);
    const fp16* yLo = y + (size_t)uLo * NN * HID_F;
    const fp16* yHi = y + (size_t)uHi * NN * HID_F;
    const float* bLo = b1 + (c * 4 + t) * HID_F;
    const float* bHi = b1 + (c * 4 + t + 2) * HID_F;

    float4 a0 = make_float4(0, 0, 0, 0), a1 = a0, e0 = a0, e1 = a0;
    float4 c0 = a0, c1 = a0, f0 = a0, f1 = a0;
    {
        int b = base[uLo * NN + d], n = cnt[uLo * NN + d];
        const int* cs = csrs + (size_t)uLo * EE;
        const float* cw = csrw + (size_t)uLo * EE;
        int i = 0;
        for (; i + 2 <= n; i += 2) {
            int s0 = cs[b + i], s1 = cs[b + i + 1];
            float w0 = cw[b + i], w1 = cw[b + i + 1];
            const uint2* r0 = (const uint2*)(yLo + (size_t)s0 * HID_F);
            const uint2* r1 = (const uint2*)(yLo + (size_t)s1 * HID_F);
            fma4h(a0, w0, r0[lane]);
            fma4h(a1, w0, r0[32 + lane]);
            fma4h(e0, w1, r1[lane]);
            fma4h(e1, w1, r1[32 + lane]);
        }
        if (i < n) {
            int s0 = cs[b + i];
            float w0 = cw[b + i];
            const uint2* r0 = (const uint2*)(yLo + (size_t)s0 * HID_F);
            fma4h(a0, w0, r0[lane]);
            fma4h(a1, w0, r0[32 + lane]);
        }
    }
    {
        int b = base[uHi * NN + d], n = cnt[uHi * NN + d];
        const int* cs = csrs + (size_t)uHi * EE;
        const float* cw = csrw + (size_t)uHi * EE;
        int i = 0;
        for (; i + 2 <= n; i += 2) {
            int s0 = cs[b + i], s1 = cs[b + i + 1];
            float w0 = cw[b + i], w1 = cw[b + i + 1];
            const uint2* r0 = (const uint2*)(yHi + (size_t)s0 * HID_F);
            const uint2* r1 = (const uint2*)(yHi + (size_t)s1 * HID_F);
            fma4h(c0, w0, r0[lane]);
            fma4h(c1, w0, r0[32 + lane]);
            fma4h(f0, w1, r1[lane]);
            fma4h(f1, w1, r1[32 + lane]);
        }
        if (i < n) {
            int s0 = cs[b + i];
            float w0 = cw[b + i];
            const uint2* r0 = (const uint2*)(yHi + (size_t)s0 * HID_F);
            fma4h(c0, w0, r0[lane]);
            fma4h(c1, w0, r0[32 + lane]);
        }
    }
    a0.x += e0.x; a0.y += e0.y; a0.z += e0.z; a0.w += e0.w;
    a1.x += e1.x; a1.y += e1.y; a1.z += e1.z; a1.w += e1.w;
    c0.x += f0.x; c0.y += f0.y; c0.z += f0.z; c0.w += f0.w;
    c1.x += f1.x; c1.y += f1.y; c1.z += f1.z; c1.w += f1.w;

    float rl = rin[uLo * NN + d], rh = rin[uHi * NN + d];
    fp16* o1 = h1 + (size_t)by * NN * HID_F;
#pragma unroll
    for (int ch = 0; ch < 2; ++ch) {
        float4 A = ch ? a1 : a0, C = ch ? c1 : c0;
        float4 x = ((const float4*)bLo)[ch * 32 + lane];
        float4 yb = ((const float4*)bHi)[ch * 32 + lane];
        float r0 = fmaxf(x.x + yb.x + rl * A.x + rh * C.x, 0.f);
        float r1 = fmaxf(x.y + yb.y + rl * A.y + rh * C.y, 0.f);
        float r2 = fmaxf(x.z + yb.z + rl * A.z + rh * C.z, 0.f);
        float r3 = fmaxf(x.w + yb.w + rl * A.w + rh * C.w, 0.f);
        __half2 p0 = __floats2half2_rn(r0, r1);
        __half2 p1 = __floats2half2_rn(r2, r3);
        uint2 st;
        st.x = *(unsigned*)&p0; st.y = *(unsigned*)&p1;
        size_t off = (size_t)d * HID_F + ch * 128 + lane * 4;
        *(uint2*)(o1 + off) = st;
    }
}

// --------- fused gather layer2 (fp16 y2 rows) + z fp16 attention rows ---------
__global__ void __launch_bounds__(256) k_gag2(
    const fp16* __restrict__ y2,
    const int* __restrict__ csrs, const float* __restrict__ csrw,
    const int* __restrict__ base, const int* __restrict__ cnt,
    const float* __restrict__ rin, const float* __restrict__ b2,
    float* __restrict__ zd, float* __restrict__ zp,
    fp16* __restrict__ za1, int ci) {
    int gw = (blockIdx.x * blockDim.x + threadIdx.x) >> 5;
    if (gw >= NN) return;
    int lane = threadIdx.x & 31;
    int d = gw;
    int t = blockIdx.y;
    int uLo = ci * 4 + t, uHi = uLo + 2;
    int c = (ci == 0) ? 0 : (ci == 1 ? 2 : 3);
    const fp16* yLo = y2 + (size_t)uLo * NN * OUT_F;
    const fp16* yHi = y2 + (size_t)uHi * NN * OUT_F;
    const float* bLo = b2 + (c * 4 + t) * OUT_F;
    const float* bHi = b2 + (c * 4 + t + 2) * OUT_F;

    float4 a0 = make_float4(0, 0, 0, 0), e0 = a0, c0 = a0, f0 = a0;
    {
        int b = base[uLo * NN + d], n = cnt[uLo * NN + d];
        const int* cs = csrs + (size_t)uLo * EE;
        const float* cw = csrw + (size_t)uLo * EE;
        int i = 0;
        for (; i + 2 <= n; i += 2) {
            fma4h(a0, cw[b + i], ((const uint2*)(yLo + (size_t)cs[b + i] * OUT_F))[lane]);
            fma4h(e0, cw[b + i + 1],
                  ((const uint2*)(yLo + (size_t)cs[b + i + 1] * OUT_F))[lane]);
        }
        if (i < n)
            fma4h(a0, cw[b + i], ((const uint2*)(yLo + (size_t)cs[b + i] * OUT_F))[lane]);
    }
    {
        int b = base[uHi * NN + d], n = cnt[uHi * NN + d];
        const int* cs = csrs + (size_t)uHi * EE;
        const float* cw = csrw + (size_t)uHi * EE;
        int i = 0;
        for (; i + 2 <= n; i += 2) {
            fma4h(c0, cw[b + i], ((const uint2*)(yHi + (size_t)cs[b + i] * OUT_F))[lane]);
            fma4h(f0, cw[b + i + 1],
                  ((const uint2*)(yHi + (size_t)cs[b + i + 1] * OUT_F))[lane]);
        }
        if (i < n)
            fma4h(c0, cw[b + i], ((const uint2*)(yHi + (size_t)cs[b + i] * OUT_F))[lane]);
    }
    a0.x += e0.x; a0.y += e0.y; a0.z += e0.z; a0.w += e0.w;
    c0.x += f0.x; c0.y += f0.y; c0.z += f0.z; c0.w += f0.w;

    float rl = rin[uLo * NN + d], rh = rin[uHi * NN + d];
    float4 x = ((const float4*)bLo)[lane], yb = ((const float4*)bHi)[lane];
    float4 res;
    res.x = fmaxf(x.x + yb.x + rl * a0.x + rh * c0.x, 0.f);
    res.y = fmaxf(x.y + yb.y + rl * a0.y + rh * c0.y, 0.f);
    res.z = fmaxf(x.z + yb.z + rl * a0.z + rh * c0.z, 0.f);
    res.w = fmaxf(x.w + yb.w + rl * a0.w + rh * c0.w, 0.f);
    float* zt = t ? zp : zd;
    *(float4*)(zt + (size_t)d * (3 * OUT_F) + ci * OUT_F + lane * 4) = res;

    size_t row = (size_t)ci * 2 * NN + (size_t)t * NN + d;
    __half2 p0 = __floats2half2_rn(res.x, res.y);
    __half2 p1 = __floats2half2_rn(res.z, res.w);
    uint2 st;
    st.x = *(unsigned*)&p0; st.y = *(unsigned*)&p1;
    *(uint2*)(za1 + row * OUT_F + lane * 4) = st;
}

// ------------- combine with fused beta (block-local softmax of wsum) -------------
__global__ void k_combine(const float* __restrict__ zd, const float* __restrict__ zp,
                          const float* __restrict__ wsum, float* __restrict__ out,
                          float* __restrict__ outBeta) {
    __shared__ float sb[6];
    if (threadIdx.x == 0) {
#pragma unroll
        for (int t = 0; t < 2; ++t) {
            float w0 = wsum[t * 3 + 0] / (float)NN;
            float w1 = wsum[t * 3 + 1] / (float)NN;
            float w2 = wsum[t * 3 + 2] / (float)NN;
            float m = fmaxf(w0, fmaxf(w1, w2));
            float e0 = expf(w0 - m), e1 = expf(w1 - m), e2 = expf(w2 - m);
            float inv = 1.f / (e0 + e1 + e2);
            sb[t * 3 + 0] = e0 * inv;
            sb[t * 3 + 1] = e1 * inv;
            sb[t * 3 + 2] = e2 * inv;
        }
    }
    __syncthreads();
    if (blockIdx.x == 0 && threadIdx.x < 6) outBeta[threadIdx.x] = sb[threadIdx.x];
    int i = blockIdx.x * blockDim.x + threadIdx.x;
    if (i >= 2 * NN * OUT_F) return;
    int t = i / (NN * OUT_F);
    int r = i - t * NN * OUT_F;
    int n = r / OUT_F, f = r - n * OUT_F;
    const float* z = (t ? zp : zd) + (size_t)n * (3 * OUT_F) + f;
    out[i] = sb[t * 3 + 0] * z[0] + sb[t * 3 + 1] * z[OUT_F] + sb[t * 3 + 2] * z[2 * OUT_F];
}

// ---------------- host orchestration ----------------
extern "C" void kernel_launch(void* const* d_in, const int* in_sizes, int n_in,
                              void* d_out, int out_size) {
    const float* xd  = (const float*)d_in[0];
    const float* xp  = (const float*)d_in[1];
    const int*   src = (const int*)  d_in[2];
    const int*   dst = (const int*)  d_in[3];
    const float* W1  = (const float*)d_in[4];
    const float* b1  = (const float*)d_in[5];
    const float* W2  = (const float*)d_in[6];
    const float* b2  = (const float*)d_in[7];
    const float* Wpm = (const float*)d_in[8];
    const float* bp  = (const float*)d_in[9];
    const float* q   = (const float*)d_in[10];
    float* out = (float*)d_out;

    float *zd, *zp, *rout, *rin, *wsum, *csrw;
    int *cnts, *cnt, *base, *cur, *csrs;
    fp16 *y, *y2, *x1, *h1, *za1;
    fp16 *wt1a, *wt2a, *wpa, *wpb;
    cudaGetSymbolAddress((void**)&y,    g_y);
    cudaGetSymbolAddress((void**)&y2,   g_y2);
    cudaGetSymbolAddress((void**)&zd,   g_zd);
    cudaGetSymbolAddress((void**)&zp,   g_zp);
    cudaGetSymbolAddress((void**)&rout, g_rout);
    cudaGetSymbolAddress((void**)&rin,  g_rin);
    cudaGetSymbolAddress((void**)&wsum, g_wsum);
    cudaGetSymbolAddress((void**)&cnts, g_cnts);
    cudaGetSymbolAddress((void**)&cnt,  g_cnt);
    cudaGetSymbolAddress((void**)&base, g_base);
    cudaGetSymbolAddress((void**)&cur,  g_cur);
    cudaGetSymbolAddress((void**)&csrs, g_csrs);
    cudaGetSymbolAddress((void**)&csrw, g_csrw);
    cudaGetSymbolAddress((void**)&x1,   g_x1);
    cudaGetSymbolAddress((void**)&h1,   g_h1);
    cudaGetSymbolAddress((void**)&za1,  g_za1);
    cudaGetSymbolAddress((void**)&wt1a, g_wt1a);
    cudaGetSymbolAddress((void**)&wt2a, g_wt2a);
    cudaGetSymbolAddress((void**)&wpa,  g_wpa);
    cudaGetSymbolAddress((void**)&wpb,  g_wpb);

    const int T = 256;
    const int mtiles = (NN + 127) / 128;            // 235
    const int gblocks = (NN * 32 + T - 1) / T;      // 3750
    cudaStream_t sd = g_ss.side;

    cudaEventRecord(g_ss.fork, 0);
    cudaStreamWaitEvent(sd, g_ss.fork, 0);
    cudaStreamWaitEvent(g_ss.sc[0], g_ss.fork, 0);

    // kernel #1: half-convert xd (main)
    k_half<<<(NN * IN_F / 4 + T - 1) / T, T>>>(xd, x1, NN * IN_F / 4);
    // kernel #2: half-convert xp (channel stream 0)
    k_half<<<(NN * IN_F / 4 + T - 1) / T, T, 0, g_ss.sc[0]>>>(
        xp, x1 + (size_t)NN * IN_F, NN * IN_F / 4);
    cudaEventRecord(g_ss.xe, g_ss.sc[0]);
    // kernel #3: W1 transform (side)
    k_wts<<<dim3(HID_F / 32, IN_F / 32, 12), dim3(32, 8), 0, sd>>>(W1, wt1a, IN_F, HID_F);
    cudaEventRecord(g_ss.w1e, sd);

    // kernel #4: GEMM1 channel 0 (ncu -s 5 -c 1 lands here)
    cudaStreamWaitEvent(0, g_ss.w1e, 0);
    cudaStreamWaitEvent(0, g_ss.xe, 0);
    k_mma<IN_F, HID_F, 0, 1, 0><<<dim3(4 * (HID_F / 128), mtiles), 256>>>(
        x1, wt1a, wt1a, y, NN, 0, 0, nullptr, nullptr, nullptr);
    cudaEventRecord(g_ss.e1[0], 0);

    // side chain: CSR build + remaining weight transforms + wsum zero
    k_zeroi2<<<(12 * NN + T - 1) / T, T, 0, sd>>>(cnts, cnt, 12 * NN);
    k_hist2<<<(12 * EE + T - 1) / T, T, 0, sd>>>(src, dst, cnts, cnt);
    k_prep<<<(12 * NN + T - 1) / T, T, 0, sd>>>(cnts, cnt, rout, rin);
    k_scan<<<12, 1024, 0, sd>>>(cnt, base, cur);
    k_fill<<<(12 * EE + T - 1) / T, T, 0, sd>>>(src, dst, rout, cur, csrs, csrw);
    k_wts<<<dim3(OUT_F / 32, HID_F / 32, 12), dim3(32, 8), 0, sd>>>(W2, wt2a, HID_F, OUT_F);
    k_wts1<<<dim3(OUT_F / 32, OUT_F / 32), dim3(32, 8), 0, sd>>>(Wpm, wpa, wpb, OUT_F, OUT_F);
    k_zero<<<1, 32, 0, sd>>>(wsum, 8);
    cudaEventRecord(g_ss.join, sd);

    // GEMM1 channels 1,2 (main)
    for (int c = 1; c < 3; ++c) {
        k_mma<IN_F, HID_F, 0, 1, 0><<<dim3(4 * (HID_F / 128), mtiles), 256>>>(
            x1, wt1a, wt1a, y, NN, c * 4, 0, nullptr, nullptr, nullptr);
        cudaEventRecord(g_ss.e1[c], 0);
    }

    // per-channel pipelines: gag1 -> GEMM2 -> gag2 -> attention GEMM
    for (int c = 0; c < 3; ++c) {
        cudaStream_t s = g_ss.sc[c];
        cudaStreamWaitEvent(s, g_ss.e1[c], 0);
        cudaStreamWaitEvent(s, g_ss.join, 0);
        k_gag1<<<dim3(gblocks, 2), T, 0, s>>>(y, csrs, csrw, base, cnt, rin, b1,
                                              h1, c);
        k_mma<HID_F, OUT_F, 1, 1, 0><<<dim3(4, mtiles), 256, 0, s>>>(
            h1, wt2a, wt2a, y2, NN, c * 4, 0, nullptr, nullptr, nullptr);
        k_gag2<<<dim3(gblocks, 2), T, 0, s>>>(y2, csrs, csrw, base, cnt, rin, b2,
                                              zd, zp, za1, c);
        k_mma<OUT_F, OUT_F, 0, 2, 1><<<dim3(1, (2 * NN + 127) / 128), 256, 0, s>>>(
            za1 + (size_t)c * 2 * NN * OUT_F, wpa, wpb,
            nullptr, 2 * NN, 0, c, bp, q, wsum);
        cudaEventRecord(g_ss.ec[c], s);
    }

    // join all channels, then fused beta+combine on main
    for (int c = 0; c < 3; ++c) cudaStreamWaitEvent(0, g_ss.ec[c], 0);
    k_combine<<<(2 * NN * OUT_F + T - 1) / T, T>>>(zd, zp, wsum, out,
                                                   out + (size_t)2 * NN * OUT_F);
}